// round 1
// baseline (speedup 1.0000x reference)
#include <cuda_runtime.h>
#include <math.h>

#define NPREDN 100000
#define NTOTN  120000
#define NITEMN 100000
#define NUIN   200000
#define NNODESN 220000
#define EMBD 64
#define MAXE 1500000

// ---------------- device scratch (static, no allocations) ----------------
__device__ float g_ebn[NNODESN*EMBD];
__device__ float g_uie[NUIN*EMBD];
__device__ float g_fs[NUIN*EMBD];
__device__ float g_fd[NUIN*EMBD];
__device__ float g_gout[NUIN*EMBD];
__device__ float g_u2i[NUIN*EMBD];
__device__ float g_rc[NUIN*EMBD];
__device__ float g_T1[NTOTN*EMBD];
__device__ float g_T2[NTOTN*EMBD];
__device__ float g_ch[NTOTN*EMBD];
__device__ float g_ch2[NTOTN*EMBD];
__device__ float g_av[NTOTN*EMBD];
__device__ float g_su[NPREDN*EMBD];
__device__ float g_i2u[NPREDN*EMBD];
__device__ float g_soc[NPREDN*EMBD];
__device__ float g_sie[NPREDN*EMBD];
__device__ float g_uitem[NPREDN*EMBD];
__device__ float g_huP[NPREDN*EMBD];
__device__ float g_huS[NPREDN*EMBD];
__device__ float g_mA[NPREDN*EMBD];
__device__ float g_z[NPREDN*EMBD];
__device__ float g_edge[MAXE];
__device__ float g_normv[MAXE];
__device__ float g_mmax[NUIN];
__device__ float g_den[NUIN];
__device__ float g_deg[NTOTN];
__device__ float g_stat[2*EMBD];

// ---------------- small helpers ----------------
__device__ __forceinline__ void atomicMaxFloat(float* addr, float val) {
    int old = __float_as_int(*addr);
    while (__int_as_float(old) < val) {
        int prev = atomicCAS((int*)addr, old, __float_as_int(val));
        if (prev == old) break;
        old = prev;
    }
}

__global__ void k_fill(float* __restrict__ p, float v, int n) {
    int i = blockIdx.x*blockDim.x + threadIdx.x;
    if (i < n) p[i] = v;
}

// ---------------- GEMM: Y[n,64] = X[n,64] @ W[64,64] (+bias) (+accum) (+lrelu) ------
__global__ void k_gemm64(const float* __restrict__ X, const float* __restrict__ W,
                         const float* __restrict__ bias, float* __restrict__ Y,
                         int n, int accum, int act)
{
    __shared__ float Ws[64][64];
    __shared__ float Xs[32][64];
    int tx = threadIdx.x & 63;   // output col
    int tg = threadIdx.x >> 6;   // 0..3
    int row0 = blockIdx.x * 32;

    for (int i = threadIdx.x; i < 64*64; i += 256) Ws[i>>6][i&63] = W[i];
    for (int i = threadIdx.x; i < 32*64; i += 256) {
        int r = i >> 6, c = i & 63;
        int gr = row0 + r;
        Xs[r][c] = (gr < n) ? X[(size_t)gr*64 + c] : 0.f;
    }
    __syncthreads();

    float acc[8];
    #pragma unroll
    for (int r = 0; r < 8; r++) acc[r] = 0.f;
    #pragma unroll 8
    for (int k = 0; k < 64; k++) {
        float w = Ws[k][tx];
        #pragma unroll
        for (int r = 0; r < 8; r++) acc[r] = fmaf(Xs[tg + r*4][k], w, acc[r]);
    }
    #pragma unroll
    for (int r = 0; r < 8; r++) {
        int gr = row0 + tg + r*4;
        if (gr < n) {
            float v = acc[r];
            if (bias) v += bias[tx];
            size_t o = (size_t)gr*64 + tx;
            if (accum) v += Y[o];
            if (act) v = v > 0.f ? v : 0.01f*v;
            Y[o] = v;
        }
    }
}

// ---------------- BN: column stats + apply ----------------
__global__ void k_colstats(const float* __restrict__ X, int n, float* __restrict__ stat)
{
    int c  = threadIdx.x & 63;
    int tg = threadIdx.x >> 6;
    float s = 0.f, sq = 0.f;
    for (int r = blockIdx.x*4 + tg; r < n; r += gridDim.x*4) {
        float v = X[(size_t)r*64 + c];
        s += v; sq += v*v;
    }
    __shared__ float sh[4][128];
    sh[tg][c] = s; sh[tg][64+c] = sq;
    __syncthreads();
    if (tg == 0) {
        float ts = sh[0][c]+sh[1][c]+sh[2][c]+sh[3][c];
        float tq = sh[0][64+c]+sh[1][64+c]+sh[2][64+c]+sh[3][64+c];
        atomicAdd(&stat[c], ts);
        atomicAdd(&stat[64+c], tq);
    }
}

__global__ void k_bnapply(const float* __restrict__ X, const float* __restrict__ stat,
                          const float* __restrict__ g, const float* __restrict__ b,
                          float* __restrict__ Y, int total, float invn, int act)
{
    int i = blockIdx.x*blockDim.x + threadIdx.x;
    if (i >= total) return;
    int c = i & 63;
    float mu = stat[c]*invn;
    float var = stat[64+c]*invn - mu*mu;
    float v = (X[i]-mu)*rsqrtf(var + 1e-5f)*g[c] + b[c];
    if (act) v = v > 0.f ? v : 0.01f*v;
    Y[i] = v;
}

// ---------------- GAT edge kernels ----------------
__global__ void k_edge_e(const int* __restrict__ src, const int* __restrict__ dst, int ne,
                         const float* __restrict__ fs, const float* __restrict__ fd,
                         const float* __restrict__ attn,
                         float* __restrict__ ev, float* __restrict__ m)
{
    int w = (blockIdx.x*blockDim.x + threadIdx.x) >> 5;
    int lane = threadIdx.x & 31;
    if (w >= ne) return;
    int s = src[w], d = dst[w];
    const float* ps = fs + (size_t)s*64;
    const float* pd = fd + (size_t)d*64;
    float acc = 0.f;
    #pragma unroll
    for (int j = 0; j < 2; j++) {
        int k = lane + j*32;
        float v = ps[k] + pd[k];
        v = v > 0.f ? v : 0.2f*v;
        acc += v * __ldg(&attn[k]);
    }
    #pragma unroll
    for (int o = 16; o; o >>= 1) acc += __shfl_xor_sync(0xffffffffu, acc, o);
    if (lane == 0) {
        ev[w] = acc;
        atomicMaxFloat(&m[d], acc);
    }
}

__global__ void k_edge_soft(const int* __restrict__ dst, int ne,
                            float* __restrict__ ev, const float* __restrict__ m,
                            float* __restrict__ den)
{
    int i = blockIdx.x*blockDim.x + threadIdx.x;
    if (i >= ne) return;
    int d = dst[i];
    float ex = __expf(ev[i] - m[d]);
    ev[i] = ex;
    atomicAdd(&den[d], ex);
}

__global__ void k_edge_aggr(const int* __restrict__ src, const int* __restrict__ dst, int ne,
                            const float* __restrict__ ev, const float* __restrict__ fs,
                            float* __restrict__ out)
{
    int w = (blockIdx.x*blockDim.x + threadIdx.x) >> 5;
    int lane = threadIdx.x & 31;
    if (w >= ne) return;
    int s = src[w], d = dst[w];
    float a = ev[w];
    const float* ps = fs + (size_t)s*64;
    float* po = out + (size_t)d*64;
    atomicAdd(&po[lane],      a*ps[lane]);
    atomicAdd(&po[lane+32],   a*ps[lane+32]);
}

__global__ void k_node_fin(float* __restrict__ out, const float* __restrict__ den, int total)
{
    int i = blockIdx.x*blockDim.x + threadIdx.x;
    if (i >= total) return;
    float d = den[i >> 6];
    float v = d > 0.f ? out[i]/d : 0.f;
    out[i] = v > 0.f ? v : 0.01f*v;
}

// ---------------- Cheb kernels ----------------
__global__ void k_deg(const int* __restrict__ dst, int ne, float* __restrict__ deg)
{
    int i = blockIdx.x*blockDim.x + threadIdx.x;
    if (i < ne) atomicAdd(&deg[dst[i]], 1.f);
}
__global__ void k_dinv(float* __restrict__ deg, int n)
{
    int i = blockIdx.x*blockDim.x + threadIdx.x;
    if (i < n) deg[i] = rsqrtf(fmaxf(deg[i], 1.f));
}
__global__ void k_normk(const int* __restrict__ src, const int* __restrict__ dst, int ne,
                        const float* __restrict__ dinv, float* __restrict__ nv)
{
    int i = blockIdx.x*blockDim.x + threadIdx.x;
    if (i < ne) nv[i] = dinv[src[i]] * dinv[dst[i]];
}
__global__ void k_lhat_edge(const int* __restrict__ src, const int* __restrict__ dst, int ne,
                            const float* __restrict__ nv, const float* __restrict__ v,
                            float* __restrict__ av)
{
    int w = (blockIdx.x*blockDim.x + threadIdx.x) >> 5;
    int lane = threadIdx.x & 31;
    if (w >= ne) return;
    int s = src[w], d = dst[w];
    float nrm = nv[w];
    const float* pv = v + (size_t)s*64;
    float* pa = av + (size_t)d*64;
    atomicAdd(&pa[lane],    nrm*pv[lane]);
    atomicAdd(&pa[lane+32], nrm*pv[lane+32]);
}
__global__ void k_lhat_fin(const float* __restrict__ v, const float* __restrict__ av,
                           const float* __restrict__ lamp, float* __restrict__ out, int total)
{
    int i = blockIdx.x*blockDim.x + threadIdx.x;
    if (i >= total) return;
    float lam = __ldg(lamp);
    out[i] = (2.f/lam)*(v[i]-av[i]) - v[i];
}
__global__ void k_comb(float* __restrict__ t2, const float* __restrict__ t0, int total)
{
    int i = blockIdx.x*blockDim.x + threadIdx.x;
    if (i < total) t2[i] = 2.f*t2[i] - t0[i];
}

// ---------------- misc data movement ----------------
__global__ void k_build_uie(const float* __restrict__ ebn, float* __restrict__ uie)
{
    int i = blockIdx.x*blockDim.x + threadIdx.x;
    if (i >= NUIN*EMBD) return;
    int row = i >> 6;
    int sr = row < NPREDN ? row : row + (NNODESN - NUIN);
    uie[i] = ebn[(size_t)sr*64 + (i & 63)];
}
__global__ void k_gather_rows(const float* __restrict__ x, const int* __restrict__ ids,
                              float* __restrict__ y, int total)
{
    int i = blockIdx.x*blockDim.x + threadIdx.x;
    if (i >= total) return;
    y[i] = x[(size_t)ids[i>>6]*64 + (i & 63)];
}
__global__ void k_copy(float* __restrict__ y, const float* __restrict__ x, int total)
{
    int i = blockIdx.x*blockDim.x + threadIdx.x;
    if (i < total) y[i] = x[i];
}
__global__ void k_soc(const float* __restrict__ i2u, const int* __restrict__ ids,
                      float* __restrict__ soc, int n)
{
    int w = (blockIdx.x*blockDim.x + threadIdx.x) >> 5;
    int lane = threadIdx.x & 31;
    if (w >= n) return;
    const float* row = i2u + (size_t)w*64;
    float a = row[lane], b = row[lane+32];
    float s = a + b;
    #pragma unroll
    for (int o = 16; o; o >>= 1) s += __shfl_xor_sync(0xffffffffu, s, o);
    if (s != 0.f) {
        int t = ids[w];
        soc[(size_t)t*64 + lane]      = a;
        soc[(size_t)t*64 + lane + 32] = b;
    }
}
__global__ void k_softmul(const float* __restrict__ hX, const float* __restrict__ hP,
                          const float* __restrict__ hS, float* __restrict__ out, int n)
{
    int w = (blockIdx.x*blockDim.x + threadIdx.x) >> 5;
    int lane = threadIdx.x & 31;
    if (w >= n) return;
    size_t base = (size_t)w*64;
    float v0 = hX[base+lane], v1 = hX[base+lane+32];
    float mx = fmaxf(v0, v1);
    #pragma unroll
    for (int o = 16; o; o >>= 1) mx = fmaxf(mx, __shfl_xor_sync(0xffffffffu, mx, o));
    float e0 = __expf(v0-mx), e1 = __expf(v1-mx);
    float s = e0 + e1;
    #pragma unroll
    for (int o = 16; o; o >>= 1) s += __shfl_xor_sync(0xffffffffu, s, o);
    float inv = 1.f/s;
    out[base+lane]      = hP[base+lane]     *hS[base+lane]     *(e0*inv);
    out[base+lane+32]   = hP[base+lane+32]  *hS[base+lane+32]  *(e1*inv);
}

// ---------------- host-side composition ----------------
static inline int ceil_div(int a, int b) { return (a + b - 1) / b; }

struct Bufs {
    float *ebn,*uie,*fs,*fd,*gout,*u2i,*rc,*T1,*T2,*ch,*ch2,*av,*su,*i2u,*soc,*sie,
          *uitem,*huP,*huS,*mA,*z,*edge,*normv,*mmax,*den,*deg,*stat;
};
static void get_bufs(Bufs& B) {
    cudaGetSymbolAddress((void**)&B.ebn,  g_ebn);
    cudaGetSymbolAddress((void**)&B.uie,  g_uie);
    cudaGetSymbolAddress((void**)&B.fs,   g_fs);
    cudaGetSymbolAddress((void**)&B.fd,   g_fd);
    cudaGetSymbolAddress((void**)&B.gout, g_gout);
    cudaGetSymbolAddress((void**)&B.u2i,  g_u2i);
    cudaGetSymbolAddress((void**)&B.rc,   g_rc);
    cudaGetSymbolAddress((void**)&B.T1,   g_T1);
    cudaGetSymbolAddress((void**)&B.T2,   g_T2);
    cudaGetSymbolAddress((void**)&B.ch,   g_ch);
    cudaGetSymbolAddress((void**)&B.ch2,  g_ch2);
    cudaGetSymbolAddress((void**)&B.av,   g_av);
    cudaGetSymbolAddress((void**)&B.su,   g_su);
    cudaGetSymbolAddress((void**)&B.i2u,  g_i2u);
    cudaGetSymbolAddress((void**)&B.soc,  g_soc);
    cudaGetSymbolAddress((void**)&B.sie,  g_sie);
    cudaGetSymbolAddress((void**)&B.uitem,g_uitem);
    cudaGetSymbolAddress((void**)&B.huP,  g_huP);
    cudaGetSymbolAddress((void**)&B.huS,  g_huS);
    cudaGetSymbolAddress((void**)&B.mA,   g_mA);
    cudaGetSymbolAddress((void**)&B.z,    g_z);
    cudaGetSymbolAddress((void**)&B.edge, g_edge);
    cudaGetSymbolAddress((void**)&B.normv,g_normv);
    cudaGetSymbolAddress((void**)&B.mmax, g_mmax);
    cudaGetSymbolAddress((void**)&B.den,  g_den);
    cudaGetSymbolAddress((void**)&B.deg,  g_deg);
    cudaGetSymbolAddress((void**)&B.stat, g_stat);
}

static void run_gat(Bufs& B, const int* src, const int* dst, int ne,
                    const float* x, int n,
                    const float* Wl, const float* bl,
                    const float* Wr, const float* br,
                    const float* attn, float* out)
{
    int gb = ceil_div(n, 32);
    k_gemm64<<<gb,256>>>(x, Wl, bl, B.fs, n, 0, 0);
    k_gemm64<<<gb,256>>>(x, Wr, br, B.fd, n, 0, 0);
    k_fill<<<ceil_div(n,256),256>>>(B.mmax, -INFINITY, n);
    cudaMemsetAsync(B.den, 0, (size_t)n*4);
    cudaMemsetAsync(out, 0, (size_t)n*EMBD*4);
    int wb = ceil_div(ne, 8);
    k_edge_e   <<<wb,256>>>(src, dst, ne, B.fs, B.fd, attn, B.edge, B.mmax);
    k_edge_soft<<<ceil_div(ne,256),256>>>(dst, ne, B.edge, B.mmax, B.den);
    k_edge_aggr<<<wb,256>>>(src, dst, ne, B.edge, B.fs, out);
    k_node_fin <<<ceil_div(n*EMBD,256),256>>>(out, B.den, n*EMBD);
}

static void run_mlp(Bufs& B, const float* A, const float* Bx, const float* W,
                    const float* b, const float* g, const float* beta,
                    float* out, int n)
{
    int gb = ceil_div(n, 32);
    k_gemm64<<<gb,256>>>(A,  W,        nullptr, B.z, n, 0, 0);
    k_gemm64<<<gb,256>>>(Bx, W + 4096, b,       B.z, n, 1, 0);
    cudaMemsetAsync(B.stat, 0, 128*4);
    k_colstats<<<512,256>>>(B.z, n, B.stat);
    k_bnapply<<<ceil_div(n*EMBD,256),256>>>(B.z, B.stat, g, beta, out, n*EMBD, 1.0f/n, 1);
}

static void run_lhat(Bufs& B, const int* src, const int* dst, int ne,
                     const float* v, const float* lam, float* out)
{
    cudaMemsetAsync(B.av, 0, (size_t)NTOTN*EMBD*4);
    k_lhat_edge<<<ceil_div(ne,8),256>>>(src, dst, ne, B.normv, v, B.av);
    k_lhat_fin<<<ceil_div(NTOTN*EMBD,256),256>>>(v, B.av, lam, out, NTOTN*EMBD);
}

extern "C" void kernel_launch(void* const* d_in, const int* in_sizes, int n_in,
                              void* d_out, int out_size)
{
    const float* emb      = (const float*)d_in[0];
    const float* bn0_g    = (const float*)d_in[1];
    const float* bn0_b    = (const float*)d_in[2];
    const float* gat_Wl   = (const float*)d_in[3];
    const float* gat_bl   = (const float*)d_in[4];
    const float* gat_Wr   = (const float*)d_in[5];
    const float* gat_br   = (const float*)d_in[6];
    const float* gat_attn = (const float*)d_in[7];
    const float* cheb_W   = (const float*)d_in[8];
    const float* cheb_b   = (const float*)d_in[9];
    const float* mlp_W    = (const float*)d_in[10];
    const float* mlp_b    = (const float*)d_in[11];
    const float* mlp_g    = (const float*)d_in[12];
    const float* mlp_beta = (const float*)d_in[13];
    const float* lam      = (const float*)d_in[14];
    const int* u2i_src = (const int*)d_in[15]; const int* u2i_dst = (const int*)d_in[16];
    const int* rc_src  = (const int*)d_in[17]; const int* rc_dst  = (const int*)d_in[18];
    const int* i2u_src = (const int*)d_in[19]; const int* i2u_dst = (const int*)d_in[20];
    const int* i2u_ids = (const int*)d_in[21];
    const int* sn_src  = (const int*)d_in[22]; const int* sn_dst  = (const int*)d_in[23];
    const int* snn_src = (const int*)d_in[24]; const int* snn_dst = (const int*)d_in[25];

    int ne_u2i = in_sizes[15], ne_rc = in_sizes[17], ne_i2u = in_sizes[19];
    int ne_sn  = in_sizes[22], ne_snn = in_sizes[24];

    float* out = (float*)d_out;
    Bufs B; get_bufs(B);

    // 1. e = BN(emb) over all nodes (no activation)
    cudaMemsetAsync(B.stat, 0, 128*4);
    k_colstats<<<512,256>>>(emb, NNODESN, B.stat);
    k_bnapply<<<ceil_div(NNODESN*EMBD,256),256>>>(emb, B.stat, bn0_g, bn0_b,
                                                  B.ebn, NNODESN*EMBD, 1.0f/NNODESN, 0);
    // 2. uie = concat(e[:PRED], e[-ITEM:])
    k_build_uie<<<ceil_div(NUIN*EMBD,256),256>>>(B.ebn, B.uie);

    // 3. GAT0 on u2i edges -> u2i_emb
    run_gat(B, u2i_src, u2i_dst, ne_u2i, B.uie, NUIN,
            gat_Wl+0*4096, gat_bl+0*64, gat_Wr+0*4096, gat_br+0*64, gat_attn+0*64, B.u2i);
    // 4. GAT1 on rc edges -> rc out (iie = first PRED rows)
    run_gat(B, rc_src, rc_dst, ne_rc, B.u2i, NUIN,
            gat_Wl+1*4096, gat_bl+1*64, gat_Wr+1*4096, gat_br+1*64, gat_attn+1*64, B.rc);

    // 5. su = uie[i2u_ids]; GAT2 -> i2u_emb
    k_gather_rows<<<ceil_div(NPREDN*EMBD,256),256>>>(B.uie, i2u_ids, B.su, NPREDN*EMBD);
    run_gat(B, i2u_src, i2u_dst, ne_i2u, B.su, NPREDN,
            gat_Wl+2*4096, gat_bl+2*64, gat_Wr+2*4096, gat_br+2*64, gat_attn+2*64, B.i2u);

    // 6. soc = uie[:PRED] with masked overwrite by i2u_emb
    k_copy<<<ceil_div(NPREDN*EMBD,256),256>>>(B.soc, B.uie, NPREDN*EMBD);
    k_soc<<<ceil_div(NPREDN,8),256>>>(B.i2u, i2u_ids, B.soc, NPREDN);

    // 7. GAT3 on sn edges -> sie
    run_gat(B, sn_src, sn_dst, ne_sn, B.soc, NPREDN,
            gat_Wl+3*4096, gat_bl+3*64, gat_Wr+3*4096, gat_br+3*64, gat_attn+3*64, B.sie);

    // 8. user_item_embed = mlp0([iie, sie])
    run_mlp(B, B.rc, B.sie, mlp_W+0*8192, mlp_b+0*64, mlp_g+0*64, mlp_beta+0*64,
            B.uitem, NPREDN);

    // 9. Cheb setup on snn graph (n = TOTAL)
    cudaMemsetAsync(B.deg, 0, NTOTN*4);
    k_deg  <<<ceil_div(ne_snn,256),256>>>(snn_dst, ne_snn, B.deg);
    k_dinv <<<ceil_div(NTOTN,256),256>>>(B.deg, NTOTN);
    k_normk<<<ceil_div(ne_snn,256),256>>>(snn_src, snn_dst, ne_snn, B.deg, B.normv);

    // 10. Cheb layer 1: T0 = e[:TOTAL] (= first NTOT rows of ebn)
    run_lhat(B, snn_src, snn_dst, ne_snn, B.ebn, lam, B.T1);
    run_lhat(B, snn_src, snn_dst, ne_snn, B.T1, lam, B.T2);
    k_comb<<<ceil_div(NTOTN*EMBD,256),256>>>(B.T2, B.ebn, NTOTN*EMBD);
    {
        int gb = ceil_div(NTOTN, 32);
        k_gemm64<<<gb,256>>>(B.ebn, cheb_W+0,     nullptr, B.ch, NTOTN, 0, 0);
        k_gemm64<<<gb,256>>>(B.T1,  cheb_W+4096,  nullptr, B.ch, NTOTN, 1, 0);
        k_gemm64<<<gb,256>>>(B.T2,  cheb_W+8192,  cheb_b,  B.ch, NTOTN, 1, 1);
    }
    // 11. Cheb layer 2: T0 = ch
    run_lhat(B, snn_src, snn_dst, ne_snn, B.ch, lam, B.T1);
    run_lhat(B, snn_src, snn_dst, ne_snn, B.T1, lam, B.T2);
    k_comb<<<ceil_div(NTOTN*EMBD,256),256>>>(B.T2, B.ch, NTOTN*EMBD);
    {
        int gb = ceil_div(NTOTN, 32);
        k_gemm64<<<gb,256>>>(B.ch,  cheb_W+0,     nullptr, B.ch2, NTOTN, 0, 0);
        k_gemm64<<<gb,256>>>(B.T1,  cheb_W+4096,  nullptr, B.ch2, NTOTN, 1, 0);
        k_gemm64<<<gb,256>>>(B.T2,  cheb_W+8192,  cheb_b,  B.ch2, NTOTN, 1, 1);
    }

    // 12. GAT4 on snn edges over ch2 -> gout; user_social_embed = gout[:PRED]
    run_gat(B, snn_src, snn_dst, ne_snn, B.ch2, NTOTN,
            gat_Wl+4*4096, gat_bl+4*64, gat_Wr+4*4096, gat_br+4*64, gat_attn+4*64, B.gout);

    // 13. h_uP = mlp1([uitem, pred_u]); h_uS = mlp2([usoc, pred_u])
    run_mlp(B, B.uitem, B.ebn, mlp_W+1*8192, mlp_b+1*64, mlp_g+1*64, mlp_beta+1*64,
            B.huP, NPREDN);
    run_mlp(B, B.gout,  B.ebn, mlp_W+2*8192, mlp_b+2*64, mlp_g+2*64, mlp_beta+2*64,
            B.huS, NPREDN);

    // 14. fused gating + final MLPs -> outputs
    k_softmul<<<ceil_div(NPREDN,8),256>>>(B.huP, B.huP, B.huS, B.mA, NPREDN);
    run_mlp(B, B.mA, B.huP, mlp_W+3*8192, mlp_b+3*64, mlp_g+3*64, mlp_beta+3*64,
            out, NPREDN);
    k_softmul<<<ceil_div(NPREDN,8),256>>>(B.huS, B.huP, B.huS, B.mA, NPREDN);
    run_mlp(B, B.mA, B.huS, mlp_W+4*8192, mlp_b+4*64, mlp_g+4*64, mlp_beta+4*64,
            out + (size_t)NPREDN*EMBD, NPREDN);
}

// round 2
// speedup vs baseline: 1.6205x; 1.6205x over previous
#include <cuda_runtime.h>
#include <math.h>

#define NPREDN 100000
#define NTOTN  120000
#define NUIN   200000
#define NNODESN 220000
#define EMBD 64
#define MAXE 1500000

// ---------------- device scratch (static, no allocations) ----------------
__device__ float g_ebn[NNODESN*EMBD];
__device__ float g_uie[NUIN*EMBD];
__device__ float g_fs[NUIN*EMBD];
__device__ float g_fd[NUIN*EMBD];
__device__ float g_gout[NUIN*EMBD];
__device__ float g_u2i[NUIN*EMBD];
__device__ float g_rc[NUIN*EMBD];
__device__ float g_T1[NTOTN*EMBD];
__device__ float g_T2[NTOTN*EMBD];
__device__ float g_ch[NTOTN*EMBD];
__device__ float g_ch2[NTOTN*EMBD];
__device__ float g_av[NTOTN*EMBD];
__device__ float g_su[NPREDN*EMBD];
__device__ float g_i2u[NPREDN*EMBD];
__device__ float g_soc[NPREDN*EMBD];
__device__ float g_sie[NPREDN*EMBD];
__device__ float g_uitem[NPREDN*EMBD];
__device__ float g_huP[NPREDN*EMBD];
__device__ float g_huS[NPREDN*EMBD];
__device__ float g_mA[NPREDN*EMBD];
__device__ float g_z[NPREDN*EMBD];
__device__ float g_normv[MAXE];
__device__ float g_den[NUIN];
__device__ float g_deg[NTOTN];
__device__ float g_stat[2*EMBD];

static inline int ceil_div(int a, int b) { return (a + b - 1) / b; }

__device__ __forceinline__ float lrelu(float v, float s) { return v > 0.f ? v : s*v; }

__device__ __forceinline__ void red_v4(float* p, float4 v) {
    asm volatile("red.global.add.v4.f32 [%0], {%1, %2, %3, %4};"
                 :: "l"(p), "f"(v.x), "f"(v.y), "f"(v.z), "f"(v.w) : "memory");
}

// ============ GEMM family: 64-row blocks, 256 thr, 4x4 register tiles ============
// thread (tx,ty): rows ty*4..+3, cols tx*4..+3

__device__ __forceinline__ void load_xtile(const float* __restrict__ X, float* Xs,
                                           int row0, int n, int tid)
{
    #pragma unroll
    for (int i = 0; i < 4; i++) {
        int idx = tid + i*256;            // float4 slot 0..1023
        int r = idx >> 4, c4 = idx & 15;
        int gr = row0 + r;
        float4 v = (gr < n) ? ((const float4*)X)[(size_t)gr*16 + c4]
                            : make_float4(0.f,0.f,0.f,0.f);
        ((float4*)Xs)[idx] = v;
    }
}
__device__ __forceinline__ void load_wtile(const float* __restrict__ W, float* Ws, int tid)
{
    #pragma unroll
    for (int i = 0; i < 4; i++)
        ((float4*)Ws)[tid + i*256] = ((const float4*)W)[tid + i*256];
}

__device__ __forceinline__ void mm_accum(const float* Xs, const float* Ws,
                                         float acc[4][4], int tx, int ty)
{
    #pragma unroll
    for (int k4 = 0; k4 < 16; k4++) {
        float4 a[4];
        #pragma unroll
        for (int i = 0; i < 4; i++)
            a[i] = *(const float4*)&Xs[(ty*4+i)*64 + k4*4];
        #pragma unroll
        for (int j = 0; j < 4; j++) {
            float4 b = *(const float4*)&Ws[(k4*4+j)*64 + tx*4];
            #pragma unroll
            for (int i = 0; i < 4; i++) {
                float av = ((const float*)&a[i])[j];
                acc[i][0] = fmaf(av, b.x, acc[i][0]);
                acc[i][1] = fmaf(av, b.y, acc[i][1]);
                acc[i][2] = fmaf(av, b.z, acc[i][2]);
                acc[i][3] = fmaf(av, b.w, acc[i][3]);
            }
        }
    }
}

__device__ __forceinline__ void store_tile(float* __restrict__ Y, float acc[4][4],
                                           const float* __restrict__ bias,
                                           int row0, int n, int tx, int ty,
                                           int accum, int act)
{
    float4 bb = bias ? ((const float4*)bias)[tx] : make_float4(0.f,0.f,0.f,0.f);
    #pragma unroll
    for (int i = 0; i < 4; i++) {
        int gr = row0 + ty*4 + i;
        if (gr < n) {
            float4 v = make_float4(acc[i][0]+bb.x, acc[i][1]+bb.y,
                                   acc[i][2]+bb.z, acc[i][3]+bb.w);
            float4* py = &((float4*)Y)[(size_t)gr*16 + tx];
            if (accum) { float4 o = *py; v.x+=o.x; v.y+=o.y; v.z+=o.z; v.w+=o.w; }
            if (act) { v.x=lrelu(v.x,0.01f); v.y=lrelu(v.y,0.01f);
                       v.z=lrelu(v.z,0.01f); v.w=lrelu(v.w,0.01f); }
            *py = v;
        }
    }
}

__global__ void k_gemm(const float* __restrict__ X, const float* __restrict__ W,
                       const float* __restrict__ bias, float* __restrict__ Y,
                       int n, int accum, int act)
{
    __shared__ float Xs[4096];
    __shared__ float Ws[4096];
    int tid = threadIdx.x, tx = tid & 15, ty = tid >> 4;
    int row0 = blockIdx.x * 64;
    load_xtile(X, Xs, row0, n, tid);
    load_wtile(W, Ws, tid);
    __syncthreads();
    float acc[4][4] = {};
    mm_accum(Xs, Ws, acc, tx, ty);
    store_tile(Y, acc, bias, row0, n, tx, ty, accum, act);
}

// fs = X@W1+b1 ; fd = X@W2+b2 (no act)
__global__ void k_gemm_dual(const float* __restrict__ X,
                            const float* __restrict__ W1, const float* __restrict__ b1,
                            float* __restrict__ Y1,
                            const float* __restrict__ W2, const float* __restrict__ b2,
                            float* __restrict__ Y2, int n)
{
    __shared__ float Xs[4096];
    __shared__ float Ws1[4096];
    __shared__ float Ws2[4096];
    int tid = threadIdx.x, tx = tid & 15, ty = tid >> 4;
    int row0 = blockIdx.x * 64;
    load_xtile(X, Xs, row0, n, tid);
    load_wtile(W1, Ws1, tid);
    load_wtile(W2, Ws2, tid);
    __syncthreads();
    float acc1[4][4] = {};
    float acc2[4][4] = {};
    #pragma unroll
    for (int k4 = 0; k4 < 16; k4++) {
        float4 a[4];
        #pragma unroll
        for (int i = 0; i < 4; i++)
            a[i] = *(const float4*)&Xs[(ty*4+i)*64 + k4*4];
        #pragma unroll
        for (int j = 0; j < 4; j++) {
            float4 b = *(const float4*)&Ws1[(k4*4+j)*64 + tx*4];
            float4 c = *(const float4*)&Ws2[(k4*4+j)*64 + tx*4];
            #pragma unroll
            for (int i = 0; i < 4; i++) {
                float av = ((const float*)&a[i])[j];
                acc1[i][0]=fmaf(av,b.x,acc1[i][0]); acc1[i][1]=fmaf(av,b.y,acc1[i][1]);
                acc1[i][2]=fmaf(av,b.z,acc1[i][2]); acc1[i][3]=fmaf(av,b.w,acc1[i][3]);
                acc2[i][0]=fmaf(av,c.x,acc2[i][0]); acc2[i][1]=fmaf(av,c.y,acc2[i][1]);
                acc2[i][2]=fmaf(av,c.z,acc2[i][2]); acc2[i][3]=fmaf(av,c.w,acc2[i][3]);
            }
        }
    }
    store_tile(Y1, acc1, b1, row0, n, tx, ty, 0, 0);
    store_tile(Y2, acc2, b2, row0, n, tx, ty, 0, 0);
}

// Y = A@W[0:64] + B@W[64:128] + bias (two phases, smem reuse)
__global__ void k_gemm_cat(const float* __restrict__ A, const float* __restrict__ Bx,
                           const float* __restrict__ W, const float* __restrict__ bias,
                           float* __restrict__ Y, int n, int act)
{
    __shared__ float Xs[4096];
    __shared__ float Ws[4096];
    int tid = threadIdx.x, tx = tid & 15, ty = tid >> 4;
    int row0 = blockIdx.x * 64;
    float acc[4][4] = {};
    load_xtile(A, Xs, row0, n, tid);
    load_wtile(W, Ws, tid);
    __syncthreads();
    mm_accum(Xs, Ws, acc, tx, ty);
    __syncthreads();
    load_xtile(Bx, Xs, row0, n, tid);
    load_wtile(W + 4096, Ws, tid);
    __syncthreads();
    mm_accum(Xs, Ws, acc, tx, ty);
    store_tile(Y, acc, bias, row0, n, tx, ty, 0, act);
}

// ---------------- BN ----------------
__global__ void k_colstats(const float* __restrict__ X, int n, float* __restrict__ stat)
{
    int c  = threadIdx.x & 63;
    int tg = threadIdx.x >> 6;
    float s = 0.f, sq = 0.f;
    for (int r = blockIdx.x*4 + tg; r < n; r += gridDim.x*4) {
        float v = X[(size_t)r*64 + c];
        s += v; sq += v*v;
    }
    __shared__ float sh[4][128];
    sh[tg][c] = s; sh[tg][64+c] = sq;
    __syncthreads();
    if (tg == 0) {
        float ts = sh[0][c]+sh[1][c]+sh[2][c]+sh[3][c];
        float tq = sh[0][64+c]+sh[1][64+c]+sh[2][64+c]+sh[3][64+c];
        atomicAdd(&stat[c], ts);
        atomicAdd(&stat[64+c], tq);
    }
}

__global__ void k_bnapply(const float* __restrict__ X, const float* __restrict__ stat,
                          const float* __restrict__ g, const float* __restrict__ b,
                          float* __restrict__ Y, int nq, float invn, int act)
{   // nq = total/4 float4s
    int i = blockIdx.x*blockDim.x + threadIdx.x;
    if (i >= nq) return;
    int c4 = i & 15;
    float4 x  = ((const float4*)X)[i];
    float4 s1 = ((const float4*)stat)[c4];
    float4 s2 = ((const float4*)stat)[16 + c4];
    float4 gg = ((const float4*)g)[c4];
    float4 bb = ((const float4*)b)[c4];
    float4 o;
    {
        float mu = s1.x*invn, var = s2.x*invn - mu*mu;
        o.x = (x.x-mu)*rsqrtf(var+1e-5f)*gg.x + bb.x;
        mu = s1.y*invn; var = s2.y*invn - mu*mu;
        o.y = (x.y-mu)*rsqrtf(var+1e-5f)*gg.y + bb.y;
        mu = s1.z*invn; var = s2.z*invn - mu*mu;
        o.z = (x.z-mu)*rsqrtf(var+1e-5f)*gg.z + bb.z;
        mu = s1.w*invn; var = s2.w*invn - mu*mu;
        o.w = (x.w-mu)*rsqrtf(var+1e-5f)*gg.w + bb.w;
    }
    if (act) { o.x=lrelu(o.x,0.01f); o.y=lrelu(o.y,0.01f);
               o.z=lrelu(o.z,0.01f); o.w=lrelu(o.w,0.01f); }
    ((float4*)Y)[i] = o;
}

// ---------------- GAT fused edge pass (half-warp per edge) ----------------
__global__ void k_gat_edge(const int* __restrict__ src, const int* __restrict__ dst, int ne,
                           const float* __restrict__ fs, const float* __restrict__ fd,
                           const float* __restrict__ attn,
                           float* __restrict__ den, float* __restrict__ out)
{
    int t = blockIdx.x*blockDim.x + threadIdx.x;
    int e = t >> 4;
    int l = t & 15;
    bool valid = e < ne;
    int ec = valid ? e : 0;
    int s = src[ec], d = dst[ec];
    float4 a  = ((const float4*)fs)[(size_t)s*16 + l];
    float4 b  = ((const float4*)fd)[(size_t)d*16 + l];
    float4 at = ((const float4*)attn)[l];
    float p = lrelu(a.x+b.x,0.2f)*at.x + lrelu(a.y+b.y,0.2f)*at.y
            + lrelu(a.z+b.z,0.2f)*at.z + lrelu(a.w+b.w,0.2f)*at.w;
    #pragma unroll
    for (int o = 8; o; o >>= 1) p += __shfl_xor_sync(0xffffffffu, p, o, 16);
    float ex = __expf(p);
    if (valid) {
        if (l == 0) atomicAdd(&den[d], ex);
        red_v4(&out[((size_t)d*16 + l)*4],
               make_float4(ex*a.x, ex*a.y, ex*a.z, ex*a.w));
    }
}

__global__ void k_node_fin(float* __restrict__ out, const float* __restrict__ den, int nq)
{
    int i = blockIdx.x*blockDim.x + threadIdx.x;
    if (i >= nq) return;
    float d = den[i >> 4];
    float4 v = ((const float4*)out)[i];
    float inv = d > 0.f ? 1.f/d : 0.f;
    v.x = lrelu(v.x*inv,0.01f); v.y = lrelu(v.y*inv,0.01f);
    v.z = lrelu(v.z*inv,0.01f); v.w = lrelu(v.w*inv,0.01f);
    ((float4*)out)[i] = v;
}

// ---------------- Cheb ----------------
__global__ void k_deg(const int* __restrict__ dst, int ne, float* __restrict__ deg)
{
    int i = blockIdx.x*blockDim.x + threadIdx.x;
    if (i < ne) atomicAdd(&deg[dst[i]], 1.f);
}
__global__ void k_dinv(float* __restrict__ deg, int n)
{
    int i = blockIdx.x*blockDim.x + threadIdx.x;
    if (i < n) deg[i] = rsqrtf(fmaxf(deg[i], 1.f));
}
__global__ void k_normk(const int* __restrict__ src, const int* __restrict__ dst, int ne,
                        const float* __restrict__ dinv, float* __restrict__ nv)
{
    int i = blockIdx.x*blockDim.x + threadIdx.x;
    if (i < ne) nv[i] = dinv[src[i]] * dinv[dst[i]];
}
__global__ void k_lhat_edge(const int* __restrict__ src, const int* __restrict__ dst, int ne,
                            const float* __restrict__ nv, const float* __restrict__ v,
                            float* __restrict__ av)
{
    int t = blockIdx.x*blockDim.x + threadIdx.x;
    int e = t >> 4;
    int l = t & 15;
    if (e >= ne) return;
    int s = src[e], d = dst[e];
    float nrm = nv[e];
    float4 x = ((const float4*)v)[(size_t)s*16 + l];
    red_v4(&av[((size_t)d*16 + l)*4],
           make_float4(nrm*x.x, nrm*x.y, nrm*x.z, nrm*x.w));
}
__global__ void k_lhat_fin(const float* __restrict__ v, const float* __restrict__ av,
                           const float* __restrict__ lamp, float* __restrict__ out, int nq)
{
    int i = blockIdx.x*blockDim.x + threadIdx.x;
    if (i >= nq) return;
    float c = 2.f / __ldg(lamp);
    float4 a = ((const float4*)v)[i];
    float4 b = ((const float4*)av)[i];
    float4 o;
    o.x = c*(a.x-b.x)-a.x; o.y = c*(a.y-b.y)-a.y;
    o.z = c*(a.z-b.z)-a.z; o.w = c*(a.w-b.w)-a.w;
    ((float4*)out)[i] = o;
}
__global__ void k_comb(float* __restrict__ t2, const float* __restrict__ t0, int nq)
{
    int i = blockIdx.x*blockDim.x + threadIdx.x;
    if (i >= nq) return;
    float4 a = ((const float4*)t2)[i];
    float4 b = ((const float4*)t0)[i];
    a.x = 2.f*a.x-b.x; a.y = 2.f*a.y-b.y; a.z = 2.f*a.z-b.z; a.w = 2.f*a.w-b.w;
    ((float4*)t2)[i] = a;
}

// ---------------- misc data movement ----------------
__global__ void k_build_uie(const float* __restrict__ ebn, float* __restrict__ uie)
{   // float4 granularity
    int i = blockIdx.x*blockDim.x + threadIdx.x;
    if (i >= NUIN*16) return;
    int row = i >> 4;
    int sr = row < NPREDN ? row : row + (NNODESN - NUIN);
    ((float4*)uie)[i] = ((const float4*)ebn)[(size_t)sr*16 + (i & 15)];
}
__global__ void k_gather_rows(const float* __restrict__ x, const int* __restrict__ ids,
                              float* __restrict__ y, int nq)
{
    int i = blockIdx.x*blockDim.x + threadIdx.x;
    if (i >= nq) return;
    ((float4*)y)[i] = ((const float4*)x)[(size_t)ids[i>>4]*16 + (i & 15)];
}
__global__ void k_copy4(float* __restrict__ y, const float* __restrict__ x, int nq)
{
    int i = blockIdx.x*blockDim.x + threadIdx.x;
    if (i < nq) ((float4*)y)[i] = ((const float4*)x)[i];
}
__global__ void k_soc(const float* __restrict__ i2u, const int* __restrict__ ids,
                      float* __restrict__ soc, int n)
{
    int t = blockIdx.x*blockDim.x + threadIdx.x;
    int r = t >> 4, l = t & 15;
    if (r >= n) return;
    float4 v = ((const float4*)i2u)[(size_t)r*16 + l];
    float s = v.x + v.y + v.z + v.w;
    #pragma unroll
    for (int o = 8; o; o >>= 1) s += __shfl_xor_sync(0xffffffffu, s, o, 16);
    if (s != 0.f) {
        int tr = ids[r];
        ((float4*)soc)[(size_t)tr*16 + l] = v;
    }
}
__global__ void k_softmul(const float* __restrict__ hX, const float* __restrict__ hP,
                          const float* __restrict__ hS, float* __restrict__ out, int n)
{
    int t = blockIdx.x*blockDim.x + threadIdx.x;
    int r = t >> 4, l = t & 15;
    bool valid = r < n;
    size_t base = (size_t)(valid ? r : 0)*16 + l;
    float4 x = ((const float4*)hX)[base];
    float m = fmaxf(fmaxf(x.x, x.y), fmaxf(x.z, x.w));
    #pragma unroll
    for (int o = 8; o; o >>= 1) m = fmaxf(m, __shfl_xor_sync(0xffffffffu, m, o, 16));
    float4 e;
    e.x = __expf(x.x-m); e.y = __expf(x.y-m); e.z = __expf(x.z-m); e.w = __expf(x.w-m);
    float s = e.x + e.y + e.z + e.w;
    #pragma unroll
    for (int o = 8; o; o >>= 1) s += __shfl_xor_sync(0xffffffffu, s, o, 16);
    if (!valid) return;
    float inv = 1.f/s;
    float4 p = ((const float4*)hP)[base];
    float4 q = ((const float4*)hS)[base];
    float4 o4;
    o4.x = p.x*q.x*e.x*inv; o4.y = p.y*q.y*e.y*inv;
    o4.z = p.z*q.z*e.z*inv; o4.w = p.w*q.w*e.w*inv;
    ((float4*)out)[base] = o4;
}

// ---------------- host-side composition ----------------
struct Bufs {
    float *ebn,*uie,*fs,*fd,*gout,*u2i,*rc,*T1,*T2,*ch,*ch2,*av,*su,*i2u,*soc,*sie,
          *uitem,*huP,*huS,*mA,*z,*normv,*den,*deg,*stat;
};
static void get_bufs(Bufs& B) {
    cudaGetSymbolAddress((void**)&B.ebn,  g_ebn);
    cudaGetSymbolAddress((void**)&B.uie,  g_uie);
    cudaGetSymbolAddress((void**)&B.fs,   g_fs);
    cudaGetSymbolAddress((void**)&B.fd,   g_fd);
    cudaGetSymbolAddress((void**)&B.gout, g_gout);
    cudaGetSymbolAddress((void**)&B.u2i,  g_u2i);
    cudaGetSymbolAddress((void**)&B.rc,   g_rc);
    cudaGetSymbolAddress((void**)&B.T1,   g_T1);
    cudaGetSymbolAddress((void**)&B.T2,   g_T2);
    cudaGetSymbolAddress((void**)&B.ch,   g_ch);
    cudaGetSymbolAddress((void**)&B.ch2,  g_ch2);
    cudaGetSymbolAddress((void**)&B.av,   g_av);
    cudaGetSymbolAddress((void**)&B.su,   g_su);
    cudaGetSymbolAddress((void**)&B.i2u,  g_i2u);
    cudaGetSymbolAddress((void**)&B.soc,  g_soc);
    cudaGetSymbolAddress((void**)&B.sie,  g_sie);
    cudaGetSymbolAddress((void**)&B.uitem,g_uitem);
    cudaGetSymbolAddress((void**)&B.huP,  g_huP);
    cudaGetSymbolAddress((void**)&B.huS,  g_huS);
    cudaGetSymbolAddress((void**)&B.mA,   g_mA);
    cudaGetSymbolAddress((void**)&B.z,    g_z);
    cudaGetSymbolAddress((void**)&B.normv,g_normv);
    cudaGetSymbolAddress((void**)&B.den,  g_den);
    cudaGetSymbolAddress((void**)&B.deg,  g_deg);
    cudaGetSymbolAddress((void**)&B.stat, g_stat);
}

static void run_gat(Bufs& B, const int* src, const int* dst, int ne,
                    const float* x, int n,
                    const float* Wl, const float* bl,
                    const float* Wr, const float* br,
                    const float* attn, float* out)
{
    k_gemm_dual<<<ceil_div(n,64),256>>>(x, Wl, bl, B.fs, Wr, br, B.fd, n);
    cudaMemsetAsync(B.den, 0, (size_t)n*4);
    cudaMemsetAsync(out, 0, (size_t)n*EMBD*4);
    k_gat_edge<<<ceil_div(ne,16),256>>>(src, dst, ne, B.fs, B.fd, attn, B.den, out);
    k_node_fin<<<ceil_div(n*16,256),256>>>(out, B.den, n*16);
}

static void run_mlp(Bufs& B, const float* A, const float* Bx, const float* W,
                    const float* b, const float* g, const float* beta,
                    float* out, int n)
{
    k_gemm_cat<<<ceil_div(n,64),256>>>(A, Bx, W, b, B.z, n, 0);
    cudaMemsetAsync(B.stat, 0, 128*4);
    k_colstats<<<512,256>>>(B.z, n, B.stat);
    k_bnapply<<<ceil_div(n*16,256),256>>>(B.z, B.stat, g, beta, out, n*16, 1.0f/n, 1);
}

static void run_lhat(Bufs& B, const int* src, const int* dst, int ne,
                     const float* v, const float* lam, float* out)
{
    cudaMemsetAsync(B.av, 0, (size_t)NTOTN*EMBD*4);
    k_lhat_edge<<<ceil_div(ne,16),256>>>(src, dst, ne, B.normv, v, B.av);
    k_lhat_fin<<<ceil_div(NTOTN*16,256),256>>>(v, B.av, lam, out, NTOTN*16);
}

extern "C" void kernel_launch(void* const* d_in, const int* in_sizes, int n_in,
                              void* d_out, int out_size)
{
    const float* emb      = (const float*)d_in[0];
    const float* bn0_g    = (const float*)d_in[1];
    const float* bn0_b    = (const float*)d_in[2];
    const float* gat_Wl   = (const float*)d_in[3];
    const float* gat_bl   = (const float*)d_in[4];
    const float* gat_Wr   = (const float*)d_in[5];
    const float* gat_br   = (const float*)d_in[6];
    const float* gat_attn = (const float*)d_in[7];
    const float* cheb_W   = (const float*)d_in[8];
    const float* cheb_b   = (const float*)d_in[9];
    const float* mlp_W    = (const float*)d_in[10];
    const float* mlp_b    = (const float*)d_in[11];
    const float* mlp_g    = (const float*)d_in[12];
    const float* mlp_beta = (const float*)d_in[13];
    const float* lam      = (const float*)d_in[14];
    const int* u2i_src = (const int*)d_in[15]; const int* u2i_dst = (const int*)d_in[16];
    const int* rc_src  = (const int*)d_in[17]; const int* rc_dst  = (const int*)d_in[18];
    const int* i2u_src = (const int*)d_in[19]; const int* i2u_dst = (const int*)d_in[20];
    const int* i2u_ids = (const int*)d_in[21];
    const int* sn_src  = (const int*)d_in[22]; const int* sn_dst  = (const int*)d_in[23];
    const int* snn_src = (const int*)d_in[24]; const int* snn_dst = (const int*)d_in[25];

    int ne_u2i = in_sizes[15], ne_rc = in_sizes[17], ne_i2u = in_sizes[19];
    int ne_sn  = in_sizes[22], ne_snn = in_sizes[24];

    float* out = (float*)d_out;
    Bufs B; get_bufs(B);

    // 1. e = BN(emb)
    cudaMemsetAsync(B.stat, 0, 128*4);
    k_colstats<<<512,256>>>(emb, NNODESN, B.stat);
    k_bnapply<<<ceil_div(NNODESN*16,256),256>>>(emb, B.stat, bn0_g, bn0_b,
                                                B.ebn, NNODESN*16, 1.0f/NNODESN, 0);
    // 2. uie = concat(e[:PRED], e[-ITEM:])
    k_build_uie<<<ceil_div(NUIN*16,256),256>>>(B.ebn, B.uie);

    // 3. GAT0 (u2i), 4. GAT1 (rc)
    run_gat(B, u2i_src, u2i_dst, ne_u2i, B.uie, NUIN,
            gat_Wl+0*4096, gat_bl+0*64, gat_Wr+0*4096, gat_br+0*64, gat_attn+0*64, B.u2i);
    run_gat(B, rc_src, rc_dst, ne_rc, B.u2i, NUIN,
            gat_Wl+1*4096, gat_bl+1*64, gat_Wr+1*4096, gat_br+1*64, gat_attn+1*64, B.rc);

    // 5. su = uie[i2u_ids]; GAT2
    k_gather_rows<<<ceil_div(NPREDN*16,256),256>>>(B.uie, i2u_ids, B.su, NPREDN*16);
    run_gat(B, i2u_src, i2u_dst, ne_i2u, B.su, NPREDN,
            gat_Wl+2*4096, gat_bl+2*64, gat_Wr+2*4096, gat_br+2*64, gat_attn+2*64, B.i2u);

    // 6. soc
    k_copy4<<<ceil_div(NPREDN*16,256),256>>>(B.soc, B.uie, NPREDN*16);
    k_soc<<<ceil_div(NPREDN*16,256),256>>>(B.i2u, i2u_ids, B.soc, NPREDN);

    // 7. GAT3 (sn)
    run_gat(B, sn_src, sn_dst, ne_sn, B.soc, NPREDN,
            gat_Wl+3*4096, gat_bl+3*64, gat_Wr+3*4096, gat_br+3*64, gat_attn+3*64, B.sie);

    // 8. user_item_embed = mlp0([iie, sie])
    run_mlp(B, B.rc, B.sie, mlp_W+0*8192, mlp_b+0*64, mlp_g+0*64, mlp_beta+0*64,
            B.uitem, NPREDN);

    // 9. Cheb setup
    cudaMemsetAsync(B.deg, 0, NTOTN*4);
    k_deg  <<<ceil_div(ne_snn,256),256>>>(snn_dst, ne_snn, B.deg);
    k_dinv <<<ceil_div(NTOTN,256),256>>>(B.deg, NTOTN);
    k_normk<<<ceil_div(ne_snn,256),256>>>(snn_src, snn_dst, ne_snn, B.deg, B.normv);

    // 10. Cheb layer 1 (T0 = ebn[:TOTAL])
    run_lhat(B, snn_src, snn_dst, ne_snn, B.ebn, lam, B.T1);
    run_lhat(B, snn_src, snn_dst, ne_snn, B.T1, lam, B.T2);
    k_comb<<<ceil_div(NTOTN*16,256),256>>>(B.T2, B.ebn, NTOTN*16);
    k_gemm_cat<<<ceil_div(NTOTN,64),256>>>(B.ebn, B.T1, cheb_W, nullptr, B.ch, NTOTN, 0);
    k_gemm    <<<ceil_div(NTOTN,64),256>>>(B.T2, cheb_W+8192, cheb_b, B.ch, NTOTN, 1, 1);

    // 11. Cheb layer 2
    run_lhat(B, snn_src, snn_dst, ne_snn, B.ch, lam, B.T1);
    run_lhat(B, snn_src, snn_dst, ne_snn, B.T1, lam, B.T2);
    k_comb<<<ceil_div(NTOTN*16,256),256>>>(B.T2, B.ch, NTOTN*16);
    k_gemm_cat<<<ceil_div(NTOTN,64),256>>>(B.ch, B.T1, cheb_W, nullptr, B.ch2, NTOTN, 0);
    k_gemm    <<<ceil_div(NTOTN,64),256>>>(B.T2, cheb_W+8192, cheb_b, B.ch2, NTOTN, 1, 1);

    // 12. GAT4 (snn) on ch2
    run_gat(B, snn_src, snn_dst, ne_snn, B.ch2, NTOTN,
            gat_Wl+4*4096, gat_bl+4*64, gat_Wr+4*4096, gat_br+4*64, gat_attn+4*64, B.gout);

    // 13. h_uP, h_uS
    run_mlp(B, B.uitem, B.ebn, mlp_W+1*8192, mlp_b+1*64, mlp_g+1*64, mlp_beta+1*64,
            B.huP, NPREDN);
    run_mlp(B, B.gout,  B.ebn, mlp_W+2*8192, mlp_b+2*64, mlp_g+2*64, mlp_beta+2*64,
            B.huS, NPREDN);

    // 14. gating + final MLPs
    k_softmul<<<ceil_div(NPREDN*16,256),256>>>(B.huP, B.huP, B.huS, B.mA, NPREDN);
    run_mlp(B, B.mA, B.huP, mlp_W+3*8192, mlp_b+3*64, mlp_g+3*64, mlp_beta+3*64,
            out, NPREDN);
    k_softmul<<<ceil_div(NPREDN*16,256),256>>>(B.huS, B.huP, B.huS, B.mA, NPREDN);
    run_mlp(B, B.mA, B.huS, mlp_W+4*8192, mlp_b+4*64, mlp_g+4*64, mlp_beta+4*64,
            out + (size_t)NPREDN*EMBD, NPREDN);
}

// round 3
// speedup vs baseline: 2.5149x; 1.5520x over previous
#include <cuda_runtime.h>
#include <math.h>

#define NPREDN 100000
#define NTOTN  120000
#define NUIN   200000
#define NNODESN 220000
#define EMBD 64
#define MAXE 1500000

// ---------------- device scratch (static, zero-initialized, no allocations) ----------------
__device__ float g_ebn[NNODESN*EMBD];
__device__ float g_uie[NUIN*EMBD];
__device__ float g_fs[NUIN*EMBD];
__device__ float g_fd[NUIN*EMBD];
__device__ float g_acc[NUIN*EMBD];     // GAT accumulator (self-resetting)
__device__ float g_gout[NUIN*EMBD];
__device__ float g_u2i[NUIN*EMBD];
__device__ float g_rc[NUIN*EMBD];
__device__ float g_T1[NTOTN*EMBD];
__device__ float g_T2[NTOTN*EMBD];
__device__ float g_ch[NTOTN*EMBD];
__device__ float g_ch2[NTOTN*EMBD];
__device__ float g_av[NTOTN*EMBD];     // lhat accumulator (self-resetting)
__device__ float g_i2u[NPREDN*EMBD];
__device__ float g_soc[NPREDN*EMBD];
__device__ float g_sie[NPREDN*EMBD];
__device__ float g_uitem[NPREDN*EMBD];
__device__ float g_huP[NPREDN*EMBD];
__device__ float g_huS[NPREDN*EMBD];
__device__ float g_mA[NPREDN*EMBD];
__device__ float g_z[NPREDN*EMBD];
__device__ float g_normv[MAXE];
__device__ float g_den[NUIN];          // self-resetting
__device__ float g_deg[NTOTN];
__device__ float g_stat[6*128];        // 6 slots of (sum[64], sumsq[64])

static inline int ceil_div(int a, int b) { return (a + b - 1) / b; }

__device__ __forceinline__ float lrelu(float v, float s) { return v > 0.f ? v : s*v; }

__device__ __forceinline__ void red_v4(float* p, float4 v) {
    asm volatile("red.global.add.v4.f32 [%0], {%1, %2, %3, %4};"
                 :: "l"(p), "f"(v.x), "f"(v.y), "f"(v.z), "f"(v.w) : "memory");
}

// ============ GEMM family: 64-row blocks, 128 threads, 8 rows x 4 cols per thread ======
// tx = tid & 15 -> cols tx*4..+3 ; ty = tid >> 4 (0..7) -> rows ty*8..+7

__device__ __forceinline__ void load_x64(const float* __restrict__ X, const int* __restrict__ ids,
                                         float* Xs, int row0, int n, int tid)
{
    #pragma unroll
    for (int i = 0; i < 8; i++) {
        int idx = tid + i*128;              // 0..1023 float4 slots
        int r = idx >> 4, c4 = idx & 15;
        int gr = row0 + r;
        float4 v = make_float4(0.f,0.f,0.f,0.f);
        if (gr < n) {
            int sr = ids ? ids[gr] : gr;
            v = ((const float4*)X)[(size_t)sr*16 + c4];
        }
        ((float4*)Xs)[idx] = v;
    }
}
// phase-2 loader for cheb: x = 2*X2 - X0
__device__ __forceinline__ void load_x64_comb(const float* __restrict__ X2,
                                              const float* __restrict__ X0,
                                              float* Xs, int row0, int n, int tid)
{
    #pragma unroll
    for (int i = 0; i < 8; i++) {
        int idx = tid + i*128;
        int r = idx >> 4, c4 = idx & 15;
        int gr = row0 + r;
        float4 v = make_float4(0.f,0.f,0.f,0.f);
        if (gr < n) {
            float4 a = ((const float4*)X2)[(size_t)gr*16 + c4];
            float4 b = ((const float4*)X0)[(size_t)gr*16 + c4];
            v = make_float4(2.f*a.x-b.x, 2.f*a.y-b.y, 2.f*a.z-b.z, 2.f*a.w-b.w);
        }
        ((float4*)Xs)[idx] = v;
    }
}
__device__ __forceinline__ void load_w64(const float* __restrict__ W, float* Ws, int tid)
{
    #pragma unroll
    for (int i = 0; i < 8; i++)
        ((float4*)Ws)[tid + i*128] = ((const float4*)W)[tid + i*128];
}

__device__ __forceinline__ void mm8x4(const float* Xs, const float* Ws,
                                      float acc[8][4], int tx, int ty)
{
    #pragma unroll 16
    for (int k = 0; k < 64; k++) {
        float4 b = *(const float4*)&Ws[k*64 + tx*4];
        #pragma unroll
        for (int i = 0; i < 8; i++) {
            float av = Xs[(ty*8+i)*64 + k];
            acc[i][0] = fmaf(av, b.x, acc[i][0]);
            acc[i][1] = fmaf(av, b.y, acc[i][1]);
            acc[i][2] = fmaf(av, b.z, acc[i][2]);
            acc[i][3] = fmaf(av, b.w, acc[i][3]);
        }
    }
}

__device__ __forceinline__ void store8x4(float* __restrict__ Y, float acc[8][4],
                                         const float* __restrict__ bias,
                                         int row0, int n, int tx, int ty, int act)
{
    float4 bb = bias ? ((const float4*)bias)[tx] : make_float4(0.f,0.f,0.f,0.f);
    #pragma unroll
    for (int i = 0; i < 8; i++) {
        int gr = row0 + ty*8 + i;
        if (gr < n) {
            float4 v = make_float4(acc[i][0]+bb.x, acc[i][1]+bb.y,
                                   acc[i][2]+bb.z, acc[i][3]+bb.w);
            if (act) { v.x=lrelu(v.x,0.01f); v.y=lrelu(v.y,0.01f);
                       v.z=lrelu(v.z,0.01f); v.w=lrelu(v.w,0.01f); }
            ((float4*)Y)[(size_t)gr*16 + tx] = v;
        }
    }
}

// column-stats epilogue: acc holds z (with bias); reduce across block, atomic to stat slot
__device__ __forceinline__ void stats_epilogue(float acc[8][4], float* sh,
                                               const float* __restrict__ bias,
                                               float* __restrict__ stat,
                                               int row0, int n, int tx, int ty, int tid)
{
    float4 bb = bias ? ((const float4*)bias)[tx] : make_float4(0.f,0.f,0.f,0.f);
    float s[4] = {0,0,0,0}, q[4] = {0,0,0,0};
    #pragma unroll
    for (int i = 0; i < 8; i++) {
        int gr = row0 + ty*8 + i;
        if (gr < n) {
            float v0 = acc[i][0]+bb.x, v1 = acc[i][1]+bb.y;
            float v2 = acc[i][2]+bb.z, v3 = acc[i][3]+bb.w;
            s[0]+=v0; s[1]+=v1; s[2]+=v2; s[3]+=v3;
            q[0]+=v0*v0; q[1]+=v1*v1; q[2]+=v2*v2; q[3]+=v3*v3;
        }
    }
    __syncthreads();           // Ws no longer needed
    #pragma unroll
    for (int k = 0; k < 4; k++) {
        sh[ty*128 + tx*8 + k]     = s[k];
        sh[ty*128 + tx*8 + 4 + k] = q[k];
    }
    __syncthreads();
    if (tid < 128) {
        float t = 0.f;
        #pragma unroll
        for (int w = 0; w < 8; w++) t += sh[w*128 + tid];
        int txx = tid >> 3, qq = tid & 7;
        int col = txx*4 + (qq & 3);
        atomicAdd(&stat[(qq < 4 ? col : 64 + col)], t);
    }
}

// fs = X@W1+b1 ; fd = X@W2+b2 (two phases), optional row gather via ids
__global__ void __launch_bounds__(128) k_gemm_dual(
    const float* __restrict__ X, const int* __restrict__ ids,
    const float* __restrict__ W1, const float* __restrict__ b1, float* __restrict__ Y1,
    const float* __restrict__ W2, const float* __restrict__ b2, float* __restrict__ Y2,
    int n)
{
    __shared__ float Xs[4096];
    __shared__ float Ws[4096];
    int tid = threadIdx.x, tx = tid & 15, ty = tid >> 4;
    int row0 = blockIdx.x * 64;
    load_x64(X, ids, Xs, row0, n, tid);
    load_w64(W1, Ws, tid);
    __syncthreads();
    {
        float acc[8][4] = {};
        mm8x4(Xs, Ws, acc, tx, ty);
        store8x4(Y1, acc, b1, row0, n, tx, ty, 0);
    }
    __syncthreads();
    load_w64(W2, Ws, tid);
    __syncthreads();
    {
        float acc[8][4] = {};
        mm8x4(Xs, Ws, acc, tx, ty);
        store8x4(Y2, acc, b2, row0, n, tx, ty, 0);
    }
}

// Y = A@W[0:64] + B@W[64:128] + bias ; optional fused col-stats
__global__ void __launch_bounds__(128) k_gemm_cat(
    const float* __restrict__ A, const float* __restrict__ Bx,
    const float* __restrict__ W, const float* __restrict__ bias,
    float* __restrict__ Y, int n, float* __restrict__ stat)
{
    __shared__ float Xs[4096];
    __shared__ float Ws[4096];
    int tid = threadIdx.x, tx = tid & 15, ty = tid >> 4;
    int row0 = blockIdx.x * 64;
    float acc[8][4] = {};
    load_x64(A, nullptr, Xs, row0, n, tid);
    load_w64(W, Ws, tid);
    __syncthreads();
    mm8x4(Xs, Ws, acc, tx, ty);
    __syncthreads();
    load_x64(Bx, nullptr, Xs, row0, n, tid);
    load_w64(W + 4096, Ws, tid);
    __syncthreads();
    mm8x4(Xs, Ws, acc, tx, ty);
    store8x4(Y, acc, bias, row0, n, tx, ty, 0);
    if (stat) stats_epilogue(acc, Ws, bias, stat, row0, n, tx, ty, tid);
}

// cheb: Y = lrelu(X0@W0 + X1@W1 + (2*X2-X0)@W2 + bias)
__global__ void __launch_bounds__(128) k_gemm_cat3(
    const float* __restrict__ X0, const float* __restrict__ X1, const float* __restrict__ X2,
    const float* __restrict__ W, const float* __restrict__ bias,
    float* __restrict__ Y, int n)
{
    __shared__ float Xs[4096];
    __shared__ float Ws[4096];
    int tid = threadIdx.x, tx = tid & 15, ty = tid >> 4;
    int row0 = blockIdx.x * 64;
    float acc[8][4] = {};
    load_x64(X0, nullptr, Xs, row0, n, tid);
    load_w64(W, Ws, tid);
    __syncthreads();
    mm8x4(Xs, Ws, acc, tx, ty);
    __syncthreads();
    load_x64(X1, nullptr, Xs, row0, n, tid);
    load_w64(W + 4096, Ws, tid);
    __syncthreads();
    mm8x4(Xs, Ws, acc, tx, ty);
    __syncthreads();
    load_x64_comb(X2, X0, Xs, row0, n, tid);
    load_w64(W + 8192, Ws, tid);
    __syncthreads();
    mm8x4(Xs, Ws, acc, tx, ty);
    store8x4(Y, acc, bias, row0, n, tx, ty, 1);
}

// ---------------- BN ----------------
__global__ void k_colstats(const float* __restrict__ X, int n, float* __restrict__ stat)
{
    int c  = threadIdx.x & 63;
    int tg = threadIdx.x >> 6;
    float s = 0.f, sq = 0.f;
    for (int r = blockIdx.x*4 + tg; r < n; r += gridDim.x*4) {
        float v = X[(size_t)r*64 + c];
        s += v; sq += v*v;
    }
    __shared__ float sh[4][128];
    sh[tg][c] = s; sh[tg][64+c] = sq;
    __syncthreads();
    if (tg == 0) {
        float ts = sh[0][c]+sh[1][c]+sh[2][c]+sh[3][c];
        float tq = sh[0][64+c]+sh[1][64+c]+sh[2][64+c]+sh[3][64+c];
        atomicAdd(&stat[c], ts);
        atomicAdd(&stat[64+c], tq);
    }
}

__device__ __forceinline__ float4 bn4(float4 x, float4 s1, float4 s2,
                                      float4 gg, float4 bb, float invn)
{
    float4 o;
    float mu = s1.x*invn, var = s2.x*invn - mu*mu;
    o.x = (x.x-mu)*rsqrtf(var+1e-5f)*gg.x + bb.x;
    mu = s1.y*invn; var = s2.y*invn - mu*mu;
    o.y = (x.y-mu)*rsqrtf(var+1e-5f)*gg.y + bb.y;
    mu = s1.z*invn; var = s2.z*invn - mu*mu;
    o.z = (x.z-mu)*rsqrtf(var+1e-5f)*gg.z + bb.z;
    mu = s1.w*invn; var = s2.w*invn - mu*mu;
    o.w = (x.w-mu)*rsqrtf(var+1e-5f)*gg.w + bb.w;
    return o;
}

__global__ void k_bnapply(const float* __restrict__ X, const float* __restrict__ stat,
                          const float* __restrict__ g, const float* __restrict__ b,
                          float* __restrict__ Y, int nq, float invn, int act)
{
    int i = blockIdx.x*blockDim.x + threadIdx.x;
    if (i >= nq) return;
    int c4 = i & 15;
    float4 o = bn4(((const float4*)X)[i], ((const float4*)stat)[c4],
                   ((const float4*)stat)[16+c4], ((const float4*)g)[c4],
                   ((const float4*)b)[c4], invn);
    if (act) { o.x=lrelu(o.x,0.01f); o.y=lrelu(o.y,0.01f);
               o.z=lrelu(o.z,0.01f); o.w=lrelu(o.w,0.01f); }
    ((float4*)Y)[i] = o;
}

// BN0 apply: writes ebn and (fused) uie = concat(e[:PRED], e[-ITEM:])
__global__ void k_bnapply_uie(const float* __restrict__ X, const float* __restrict__ stat,
                              const float* __restrict__ g, const float* __restrict__ b,
                              float* __restrict__ ebn, float* __restrict__ uie, float invn)
{
    int i = blockIdx.x*blockDim.x + threadIdx.x;
    if (i >= NNODESN*16) return;
    int c4 = i & 15;
    float4 o = bn4(((const float4*)X)[i], ((const float4*)stat)[c4],
                   ((const float4*)stat)[16+c4], ((const float4*)g)[c4],
                   ((const float4*)b)[c4], invn);
    ((float4*)ebn)[i] = o;
    int row = i >> 4;
    if (row < NPREDN) ((float4*)uie)[i] = o;
    else if (row >= NNODESN - 100000)  // last ITEM rows
        ((float4*)uie)[(size_t)(row - (NNODESN - NUIN))*16 + c4] = o;
}

// ---------------- GAT fused edge pass (16 threads per edge) ----------------
__global__ void k_gat_edge(const int* __restrict__ src, const int* __restrict__ dst, int ne,
                           const float* __restrict__ fs, const float* __restrict__ fd,
                           const float* __restrict__ attn,
                           float* __restrict__ den, float* __restrict__ acc)
{
    int t = blockIdx.x*blockDim.x + threadIdx.x;
    int e = t >> 4;
    int l = t & 15;
    bool valid = e < ne;
    int ec = valid ? e : 0;
    int s = src[ec], d = dst[ec];
    float4 a  = ((const float4*)fs)[(size_t)s*16 + l];
    float4 b  = ((const float4*)fd)[(size_t)d*16 + l];
    float4 at = ((const float4*)attn)[l];
    float p = lrelu(a.x+b.x,0.2f)*at.x + lrelu(a.y+b.y,0.2f)*at.y
            + lrelu(a.z+b.z,0.2f)*at.z + lrelu(a.w+b.w,0.2f)*at.w;
    #pragma unroll
    for (int o = 8; o; o >>= 1) p += __shfl_xor_sync(0xffffffffu, p, o, 16);
    float ex = __expf(p);
    if (valid) {
        if (l == 0) atomicAdd(&den[d], ex);
        red_v4(&acc[((size_t)d*16 + l)*4],
               make_float4(ex*a.x, ex*a.y, ex*a.z, ex*a.w));
    }
}

// drain accumulator -> out, reset acc and den to zero for next use
__global__ void k_node_fin(float* __restrict__ acc, float* __restrict__ den,
                           float* __restrict__ out, int nq)
{
    int i = blockIdx.x*blockDim.x + threadIdx.x;
    if (i >= nq) return;
    float d = den[i >> 4];
    float4 v = ((const float4*)acc)[i];
    float inv = d > 0.f ? 1.f/d : 0.f;
    v.x = lrelu(v.x*inv,0.01f); v.y = lrelu(v.y*inv,0.01f);
    v.z = lrelu(v.z*inv,0.01f); v.w = lrelu(v.w*inv,0.01f);
    ((float4*)out)[i] = v;
    ((float4*)acc)[i] = make_float4(0.f,0.f,0.f,0.f);
    __syncwarp();
    if ((i & 15) == 0) den[i >> 4] = 0.f;
}

// ---------------- Cheb ----------------
__global__ void k_deg(const int* __restrict__ dst, int ne, float* __restrict__ deg)
{
    int i = blockIdx.x*blockDim.x + threadIdx.x;
    if (i < ne) atomicAdd(&deg[dst[i]], 1.f);
}
__global__ void k_normk(const int* __restrict__ src, const int* __restrict__ dst, int ne,
                        const float* __restrict__ deg, float* __restrict__ nv)
{
    int i = blockIdx.x*blockDim.x + threadIdx.x;
    if (i >= ne) return;
    float ds = rsqrtf(fmaxf(deg[src[i]], 1.f));
    float dd = rsqrtf(fmaxf(deg[dst[i]], 1.f));
    nv[i] = ds * dd;
}
__global__ void k_lhat_edge(const int* __restrict__ src, const int* __restrict__ dst, int ne,
                            const float* __restrict__ nv, const float* __restrict__ v,
                            float* __restrict__ av)
{
    int t = blockIdx.x*blockDim.x + threadIdx.x;
    int e = t >> 4;
    int l = t & 15;
    if (e >= ne) return;
    int s = src[e], d = dst[e];
    float nrm = nv[e];
    float4 x = ((const float4*)v)[(size_t)s*16 + l];
    red_v4(&av[((size_t)d*16 + l)*4],
           make_float4(nrm*x.x, nrm*x.y, nrm*x.z, nrm*x.w));
}
// out = (2/lam)*(v-av) - v ; resets av to zero
__global__ void k_lhat_fin(const float* __restrict__ v, float* __restrict__ av,
                           const float* __restrict__ lamp, float* __restrict__ out, int nq)
{
    int i = blockIdx.x*blockDim.x + threadIdx.x;
    if (i >= nq) return;
    float c = 2.f / __ldg(lamp);
    float4 a = ((const float4*)v)[i];
    float4 b = ((const float4*)av)[i];
    float4 o;
    o.x = c*(a.x-b.x)-a.x; o.y = c*(a.y-b.y)-a.y;
    o.z = c*(a.z-b.z)-a.z; o.w = c*(a.w-b.w)-a.w;
    ((float4*)out)[i] = o;
    ((float4*)av)[i] = make_float4(0.f,0.f,0.f,0.f);
}

// ---------------- misc ----------------
__global__ void k_copy4(float* __restrict__ y, const float* __restrict__ x, int nq)
{
    int i = blockIdx.x*blockDim.x + threadIdx.x;
    if (i < nq) ((float4*)y)[i] = ((const float4*)x)[i];
}
__global__ void k_soc(const float* __restrict__ i2u, const int* __restrict__ ids,
                      float* __restrict__ soc, int n)
{
    int t = blockIdx.x*blockDim.x + threadIdx.x;
    int r = t >> 4, l = t & 15;
    if (r >= n) return;
    float4 v = ((const float4*)i2u)[(size_t)r*16 + l];
    float s = v.x + v.y + v.z + v.w;
    #pragma unroll
    for (int o = 8; o; o >>= 1) s += __shfl_xor_sync(0xffffffffu, s, o, 16);
    if (s != 0.f) {
        int tr = ids[r];
        ((float4*)soc)[(size_t)tr*16 + l] = v;
    }
}
__global__ void k_softmul(const float* __restrict__ hX, const float* __restrict__ hP,
                          const float* __restrict__ hS, float* __restrict__ out, int n)
{
    int t = blockIdx.x*blockDim.x + threadIdx.x;
    int r = t >> 4, l = t & 15;
    bool valid = r < n;
    size_t base = (size_t)(valid ? r : 0)*16 + l;
    float4 x = ((const float4*)hX)[base];
    float m = fmaxf(fmaxf(x.x, x.y), fmaxf(x.z, x.w));
    #pragma unroll
    for (int o = 8; o; o >>= 1) m = fmaxf(m, __shfl_xor_sync(0xffffffffu, m, o, 16));
    float4 e;
    e.x = __expf(x.x-m); e.y = __expf(x.y-m); e.z = __expf(x.z-m); e.w = __expf(x.w-m);
    float s = e.x + e.y + e.z + e.w;
    #pragma unroll
    for (int o = 8; o; o >>= 1) s += __shfl_xor_sync(0xffffffffu, s, o, 16);
    if (!valid) return;
    float inv = 1.f/s;
    float4 p = ((const float4*)hP)[base];
    float4 q = ((const float4*)hS)[base];
    ((float4*)out)[base] = make_float4(p.x*q.x*e.x*inv, p.y*q.y*e.y*inv,
                                       p.z*q.z*e.z*inv, p.w*q.w*e.w*inv);
}

// ---------------- host-side composition ----------------
struct Bufs {
    float *ebn,*uie,*fs,*fd,*acc,*gout,*u2i,*rc,*T1,*T2,*ch,*ch2,*av,*i2u,*soc,*sie,
          *uitem,*huP,*huS,*mA,*z,*normv,*den,*deg,*stat;
};
static void get_bufs(Bufs& B) {
    cudaGetSymbolAddress((void**)&B.ebn,  g_ebn);
    cudaGetSymbolAddress((void**)&B.uie,  g_uie);
    cudaGetSymbolAddress((void**)&B.fs,   g_fs);
    cudaGetSymbolAddress((void**)&B.fd,   g_fd);
    cudaGetSymbolAddress((void**)&B.acc,  g_acc);
    cudaGetSymbolAddress((void**)&B.gout, g_gout);
    cudaGetSymbolAddress((void**)&B.u2i,  g_u2i);
    cudaGetSymbolAddress((void**)&B.rc,   g_rc);
    cudaGetSymbolAddress((void**)&B.T1,   g_T1);
    cudaGetSymbolAddress((void**)&B.T2,   g_T2);
    cudaGetSymbolAddress((void**)&B.ch,   g_ch);
    cudaGetSymbolAddress((void**)&B.ch2,  g_ch2);
    cudaGetSymbolAddress((void**)&B.av,   g_av);
    cudaGetSymbolAddress((void**)&B.i2u,  g_i2u);
    cudaGetSymbolAddress((void**)&B.soc,  g_soc);
    cudaGetSymbolAddress((void**)&B.sie,  g_sie);
    cudaGetSymbolAddress((void**)&B.uitem,g_uitem);
    cudaGetSymbolAddress((void**)&B.huP,  g_huP);
    cudaGetSymbolAddress((void**)&B.huS,  g_huS);
    cudaGetSymbolAddress((void**)&B.mA,   g_mA);
    cudaGetSymbolAddress((void**)&B.z,    g_z);
    cudaGetSymbolAddress((void**)&B.normv,g_normv);
    cudaGetSymbolAddress((void**)&B.den,  g_den);
    cudaGetSymbolAddress((void**)&B.deg,  g_deg);
    cudaGetSymbolAddress((void**)&B.stat, g_stat);
}

static void run_gat(Bufs& B, const int* src, const int* dst, int ne,
                    const float* x, const int* ids, int n,
                    const float* Wl, const float* bl,
                    const float* Wr, const float* br,
                    const float* attn, float* out)
{
    k_gemm_dual<<<ceil_div(n,64),128>>>(x, ids, Wl, bl, B.fs, Wr, br, B.fd, n);
    k_gat_edge<<<ceil_div(ne,16),256>>>(src, dst, ne, B.fs, B.fd, attn, B.den, B.acc);
    k_node_fin<<<ceil_div(n*16,256),256>>>(B.acc, B.den, out, n*16);
}

static void run_mlp(Bufs& B, const float* A, const float* Bx, const float* W,
                    const float* b, const float* g, const float* beta,
                    float* out, int n, float* stat)
{
    k_gemm_cat<<<ceil_div(n,64),128>>>(A, Bx, W, b, B.z, n, stat);
    k_bnapply<<<ceil_div(n*16,256),256>>>(B.z, stat, g, beta, out, n*16, 1.0f/n, 1);
}

static void run_lhat(Bufs& B, const int* src, const int* dst, int ne,
                     const float* v, const float* lam, float* out)
{
    k_lhat_edge<<<ceil_div(ne,16),256>>>(src, dst, ne, B.normv, v, B.av);
    k_lhat_fin<<<ceil_div(NTOTN*16,256),256>>>(v, B.av, lam, out, NTOTN*16);
}

extern "C" void kernel_launch(void* const* d_in, const int* in_sizes, int n_in,
                              void* d_out, int out_size)
{
    const float* emb      = (const float*)d_in[0];
    const float* bn0_g    = (const float*)d_in[1];
    const float* bn0_b    = (const float*)d_in[2];
    const float* gat_Wl   = (const float*)d_in[3];
    const float* gat_bl   = (const float*)d_in[4];
    const float* gat_Wr   = (const float*)d_in[5];
    const float* gat_br   = (const float*)d_in[6];
    const float* gat_attn = (const float*)d_in[7];
    const float* cheb_W   = (const float*)d_in[8];
    const float* cheb_b   = (const float*)d_in[9];
    const float* mlp_W    = (const float*)d_in[10];
    const float* mlp_b    = (const float*)d_in[11];
    const float* mlp_g    = (const float*)d_in[12];
    const float* mlp_beta = (const float*)d_in[13];
    const float* lam      = (const float*)d_in[14];
    const int* u2i_src = (const int*)d_in[15]; const int* u2i_dst = (const int*)d_in[16];
    const int* rc_src  = (const int*)d_in[17]; const int* rc_dst  = (const int*)d_in[18];
    const int* i2u_src = (const int*)d_in[19]; const int* i2u_dst = (const int*)d_in[20];
    const int* i2u_ids = (const int*)d_in[21];
    const int* sn_src  = (const int*)d_in[22]; const int* sn_dst  = (const int*)d_in[23];
    const int* snn_src = (const int*)d_in[24]; const int* snn_dst = (const int*)d_in[25];

    int ne_u2i = in_sizes[15], ne_rc = in_sizes[17], ne_i2u = in_sizes[19];
    int ne_sn  = in_sizes[22], ne_snn = in_sizes[24];

    float* out = (float*)d_out;
    Bufs B; get_bufs(B);

    // stat slots: 0=BN0, 1..5 = MLP0..4
    cudaMemsetAsync(B.stat, 0, 6*128*4);

    // 1. e = BN(emb); fused uie = concat(e[:PRED], e[-ITEM:])
    k_colstats<<<512,256>>>(emb, NNODESN, B.stat);
    k_bnapply_uie<<<ceil_div(NNODESN*16,256),256>>>(emb, B.stat, bn0_g, bn0_b,
                                                    B.ebn, B.uie, 1.0f/NNODESN);

    // 2. GAT0 (u2i), GAT1 (rc)
    run_gat(B, u2i_src, u2i_dst, ne_u2i, B.uie, nullptr, NUIN,
            gat_Wl+0*4096, gat_bl+0*64, gat_Wr+0*4096, gat_br+0*64, gat_attn+0*64, B.u2i);
    run_gat(B, rc_src, rc_dst, ne_rc, B.u2i, nullptr, NUIN,
            gat_Wl+1*4096, gat_bl+1*64, gat_Wr+1*4096, gat_br+1*64, gat_attn+1*64, B.rc);

    // 3. GAT2 on su = uie[i2u_ids] (gather fused into gemm)
    run_gat(B, i2u_src, i2u_dst, ne_i2u, B.uie, i2u_ids, NPREDN,
            gat_Wl+2*4096, gat_bl+2*64, gat_Wr+2*4096, gat_br+2*64, gat_attn+2*64, B.i2u);

    // 4. soc
    k_copy4<<<ceil_div(NPREDN*16,256),256>>>(B.soc, B.uie, NPREDN*16);
    k_soc<<<ceil_div(NPREDN*16,256),256>>>(B.i2u, i2u_ids, B.soc, NPREDN);

    // 5. GAT3 (sn)
    run_gat(B, sn_src, sn_dst, ne_sn, B.soc, nullptr, NPREDN,
            gat_Wl+3*4096, gat_bl+3*64, gat_Wr+3*4096, gat_br+3*64, gat_attn+3*64, B.sie);

    // 6. user_item_embed = mlp0([iie, sie])
    run_mlp(B, B.rc, B.sie, mlp_W+0*8192, mlp_b+0*64, mlp_g+0*64, mlp_beta+0*64,
            B.uitem, NPREDN, B.stat + 128);

    // 7. Cheb norm setup
    cudaMemsetAsync(B.deg, 0, NTOTN*4);
    k_deg  <<<ceil_div(ne_snn,256),256>>>(snn_dst, ne_snn, B.deg);
    k_normk<<<ceil_div(ne_snn,256),256>>>(snn_src, snn_dst, ne_snn, B.deg, B.normv);

    // 8. Cheb layer 1 (T0 = ebn[:TOTAL])
    run_lhat(B, snn_src, snn_dst, ne_snn, B.ebn, lam, B.T1);
    run_lhat(B, snn_src, snn_dst, ne_snn, B.T1, lam, B.T2);
    k_gemm_cat3<<<ceil_div(NTOTN,64),128>>>(B.ebn, B.T1, B.T2, cheb_W, cheb_b, B.ch, NTOTN);

    // 9. Cheb layer 2
    run_lhat(B, snn_src, snn_dst, ne_snn, B.ch, lam, B.T1);
    run_lhat(B, snn_src, snn_dst, ne_snn, B.T1, lam, B.T2);
    k_gemm_cat3<<<ceil_div(NTOTN,64),128>>>(B.ch, B.T1, B.T2, cheb_W, cheb_b, B.ch2, NTOTN);

    // 10. GAT4 (snn)
    run_gat(B, snn_src, snn_dst, ne_snn, B.ch2, nullptr, NTOTN,
            gat_Wl+4*4096, gat_bl+4*64, gat_Wr+4*4096, gat_br+4*64, gat_attn+4*64, B.gout);

    // 11. h_uP, h_uS
    run_mlp(B, B.uitem, B.ebn, mlp_W+1*8192, mlp_b+1*64, mlp_g+1*64, mlp_beta+1*64,
            B.huP, NPREDN, B.stat + 2*128);
    run_mlp(B, B.gout,  B.ebn, mlp_W+2*8192, mlp_b+2*64, mlp_g+2*64, mlp_beta+2*64,
            B.huS, NPREDN, B.stat + 3*128);

    // 12. gating + final MLPs
    k_softmul<<<ceil_div(NPREDN*16,256),256>>>(B.huP, B.huP, B.huS, B.mA, NPREDN);
    run_mlp(B, B.mA, B.huP, mlp_W+3*8192, mlp_b+3*64, mlp_g+3*64, mlp_beta+3*64,
            out, NPREDN, B.stat + 4*128);
    k_softmul<<<ceil_div(NPREDN*16,256),256>>>(B.huS, B.huP, B.huS, B.mA, NPREDN);
    run_mlp(B, B.mA, B.huS, mlp_W+4*8192, mlp_b+4*64, mlp_g+4*64, mlp_beta+4*64,
            out + (size_t)NPREDN*EMBD, NPREDN, B.stat + 5*128);
}

// round 4
// speedup vs baseline: 3.0914x; 1.2292x over previous
#include <cuda_runtime.h>
#include <math.h>

#define NPREDN 100000
#define NTOTN  120000
#define NUIN   200000
#define NNODESN 220000
#define EMBD 64
#define MAXE 1500000
#define RPSZ 200001

// ---------------- device scratch (static, no allocations) ----------------
__device__ float g_ebn[NNODESN*EMBD];
__device__ float g_uie[NUIN*EMBD];
__device__ float g_fs[NUIN*EMBD];
__device__ float g_fd[NUIN*EMBD];
__device__ float g_gout[NUIN*EMBD];
__device__ float g_u2i[NUIN*EMBD];
__device__ float g_rc[NUIN*EMBD];
__device__ float g_T1[NTOTN*EMBD];
__device__ float g_T2[NTOTN*EMBD];
__device__ float g_ch[NTOTN*EMBD];
__device__ float g_ch2[NTOTN*EMBD];
__device__ float g_i2u[NPREDN*EMBD];
__device__ float g_soc[NPREDN*EMBD];
__device__ float g_sie[NPREDN*EMBD];
__device__ float g_uitem[NPREDN*EMBD];
__device__ float g_huP[NPREDN*EMBD];
__device__ float g_huS[NPREDN*EMBD];
__device__ float g_mA[NPREDN*EMBD];
__device__ float g_z[NPREDN*EMBD];
__device__ float g_stat[6*128];
// CSR sort scratch
__device__ int   g_srcs[7000000];      // 5 graphs: 1.5+1.5+1+1+1.5 M
__device__ int   g_rowptr[5*RPSZ];
__device__ int   g_cnt[RPSZ];
__device__ int   g_pos[RPSZ];
__device__ int   g_part[256];
__device__ float g_deginv[NTOTN];
__device__ float g_normv[MAXE];

static inline int ceil_div(int a, int b) { return (a + b - 1) / b; }

__device__ __forceinline__ float lrelu(float v, float s) { return v > 0.f ? v : s*v; }

// ============ GEMM family: 64-row blocks, 128 threads, 8 rows x 4 cols per thread ======
__device__ __forceinline__ void load_x64(const float* __restrict__ X, const int* __restrict__ ids,
                                         float* Xs, int row0, int n, int tid)
{
    #pragma unroll
    for (int i = 0; i < 8; i++) {
        int idx = tid + i*128;
        int r = idx >> 4, c4 = idx & 15;
        int gr = row0 + r;
        float4 v = make_float4(0.f,0.f,0.f,0.f);
        if (gr < n) {
            int sr = ids ? ids[gr] : gr;
            v = ((const float4*)X)[(size_t)sr*16 + c4];
        }
        ((float4*)Xs)[idx] = v;
    }
}
__device__ __forceinline__ void load_x64_comb(const float* __restrict__ X2,
                                              const float* __restrict__ X0,
                                              float* Xs, int row0, int n, int tid)
{
    #pragma unroll
    for (int i = 0; i < 8; i++) {
        int idx = tid + i*128;
        int r = idx >> 4, c4 = idx & 15;
        int gr = row0 + r;
        float4 v = make_float4(0.f,0.f,0.f,0.f);
        if (gr < n) {
            float4 a = ((const float4*)X2)[(size_t)gr*16 + c4];
            float4 b = ((const float4*)X0)[(size_t)gr*16 + c4];
            v = make_float4(2.f*a.x-b.x, 2.f*a.y-b.y, 2.f*a.z-b.z, 2.f*a.w-b.w);
        }
        ((float4*)Xs)[idx] = v;
    }
}
__device__ __forceinline__ void load_w64(const float* __restrict__ W, float* Ws, int tid)
{
    #pragma unroll
    for (int i = 0; i < 8; i++)
        ((float4*)Ws)[tid + i*128] = ((const float4*)W)[tid + i*128];
}

__device__ __forceinline__ void mm8x4(const float* Xs, const float* Ws,
                                      float acc[8][4], int tx, int ty)
{
    #pragma unroll 16
    for (int k = 0; k < 64; k++) {
        float4 b = *(const float4*)&Ws[k*64 + tx*4];
        #pragma unroll
        for (int i = 0; i < 8; i++) {
            float av = Xs[(ty*8+i)*64 + k];
            acc[i][0] = fmaf(av, b.x, acc[i][0]);
            acc[i][1] = fmaf(av, b.y, acc[i][1]);
            acc[i][2] = fmaf(av, b.z, acc[i][2]);
            acc[i][3] = fmaf(av, b.w, acc[i][3]);
        }
    }
}

__device__ __forceinline__ void store8x4(float* __restrict__ Y, float acc[8][4],
                                         const float* __restrict__ bias,
                                         int row0, int n, int tx, int ty, int act)
{
    float4 bb = bias ? ((const float4*)bias)[tx] : make_float4(0.f,0.f,0.f,0.f);
    #pragma unroll
    for (int i = 0; i < 8; i++) {
        int gr = row0 + ty*8 + i;
        if (gr < n) {
            float4 v = make_float4(acc[i][0]+bb.x, acc[i][1]+bb.y,
                                   acc[i][2]+bb.z, acc[i][3]+bb.w);
            if (act) { v.x=lrelu(v.x,0.01f); v.y=lrelu(v.y,0.01f);
                       v.z=lrelu(v.z,0.01f); v.w=lrelu(v.w,0.01f); }
            ((float4*)Y)[(size_t)gr*16 + tx] = v;
        }
    }
}

__device__ __forceinline__ void stats_epilogue(float acc[8][4], float* sh,
                                               const float* __restrict__ bias,
                                               float* __restrict__ stat,
                                               int row0, int n, int tx, int ty, int tid)
{
    float4 bb = bias ? ((const float4*)bias)[tx] : make_float4(0.f,0.f,0.f,0.f);
    float s[4] = {0,0,0,0}, q[4] = {0,0,0,0};
    #pragma unroll
    for (int i = 0; i < 8; i++) {
        int gr = row0 + ty*8 + i;
        if (gr < n) {
            float v0 = acc[i][0]+bb.x, v1 = acc[i][1]+bb.y;
            float v2 = acc[i][2]+bb.z, v3 = acc[i][3]+bb.w;
            s[0]+=v0; s[1]+=v1; s[2]+=v2; s[3]+=v3;
            q[0]+=v0*v0; q[1]+=v1*v1; q[2]+=v2*v2; q[3]+=v3*v3;
        }
    }
    __syncthreads();
    #pragma unroll
    for (int k = 0; k < 4; k++) {
        sh[ty*128 + tx*8 + k]     = s[k];
        sh[ty*128 + tx*8 + 4 + k] = q[k];
    }
    __syncthreads();
    if (tid < 128) {
        float t = 0.f;
        #pragma unroll
        for (int w = 0; w < 8; w++) t += sh[w*128 + tid];
        int txx = tid >> 3, qq = tid & 7;
        int col = txx*4 + (qq & 3);
        atomicAdd(&stat[(qq < 4 ? col : 64 + col)], t);
    }
}

__global__ void __launch_bounds__(128) k_gemm_dual(
    const float* __restrict__ X, const int* __restrict__ ids,
    const float* __restrict__ W1, const float* __restrict__ b1, float* __restrict__ Y1,
    const float* __restrict__ W2, const float* __restrict__ b2, float* __restrict__ Y2,
    int n)
{
    __shared__ float Xs[4096];
    __shared__ float Ws[4096];
    int tid = threadIdx.x, tx = tid & 15, ty = tid >> 4;
    int row0 = blockIdx.x * 64;
    load_x64(X, ids, Xs, row0, n, tid);
    load_w64(W1, Ws, tid);
    __syncthreads();
    {
        float acc[8][4] = {};
        mm8x4(Xs, Ws, acc, tx, ty);
        store8x4(Y1, acc, b1, row0, n, tx, ty, 0);
    }
    __syncthreads();
    load_w64(W2, Ws, tid);
    __syncthreads();
    {
        float acc[8][4] = {};
        mm8x4(Xs, Ws, acc, tx, ty);
        store8x4(Y2, acc, b2, row0, n, tx, ty, 0);
    }
}

__global__ void __launch_bounds__(128) k_gemm_cat(
    const float* __restrict__ A, const float* __restrict__ Bx,
    const float* __restrict__ W, const float* __restrict__ bias,
    float* __restrict__ Y, int n, float* __restrict__ stat)
{
    __shared__ float Xs[4096];
    __shared__ float Ws[4096];
    int tid = threadIdx.x, tx = tid & 15, ty = tid >> 4;
    int row0 = blockIdx.x * 64;
    float acc[8][4] = {};
    load_x64(A, nullptr, Xs, row0, n, tid);
    load_w64(W, Ws, tid);
    __syncthreads();
    mm8x4(Xs, Ws, acc, tx, ty);
    __syncthreads();
    load_x64(Bx, nullptr, Xs, row0, n, tid);
    load_w64(W + 4096, Ws, tid);
    __syncthreads();
    mm8x4(Xs, Ws, acc, tx, ty);
    store8x4(Y, acc, bias, row0, n, tx, ty, 0);
    if (stat) stats_epilogue(acc, Ws, bias, stat, row0, n, tx, ty, tid);
}

__global__ void __launch_bounds__(128) k_gemm_cat3(
    const float* __restrict__ X0, const float* __restrict__ X1, const float* __restrict__ X2,
    const float* __restrict__ W, const float* __restrict__ bias,
    float* __restrict__ Y, int n)
{
    __shared__ float Xs[4096];
    __shared__ float Ws[4096];
    int tid = threadIdx.x, tx = tid & 15, ty = tid >> 4;
    int row0 = blockIdx.x * 64;
    float acc[8][4] = {};
    load_x64(X0, nullptr, Xs, row0, n, tid);
    load_w64(W, Ws, tid);
    __syncthreads();
    mm8x4(Xs, Ws, acc, tx, ty);
    __syncthreads();
    load_x64(X1, nullptr, Xs, row0, n, tid);
    load_w64(W + 4096, Ws, tid);
    __syncthreads();
    mm8x4(Xs, Ws, acc, tx, ty);
    __syncthreads();
    load_x64_comb(X2, X0, Xs, row0, n, tid);
    load_w64(W + 8192, Ws, tid);
    __syncthreads();
    mm8x4(Xs, Ws, acc, tx, ty);
    store8x4(Y, acc, bias, row0, n, tx, ty, 1);
}

// ---------------- BN ----------------
__global__ void k_colstats(const float* __restrict__ X, int n, float* __restrict__ stat)
{
    int c  = threadIdx.x & 63;
    int tg = threadIdx.x >> 6;
    float s = 0.f, sq = 0.f;
    for (int r = blockIdx.x*4 + tg; r < n; r += gridDim.x*4) {
        float v = X[(size_t)r*64 + c];
        s += v; sq += v*v;
    }
    __shared__ float sh[4][128];
    sh[tg][c] = s; sh[tg][64+c] = sq;
    __syncthreads();
    if (tg == 0) {
        float ts = sh[0][c]+sh[1][c]+sh[2][c]+sh[3][c];
        float tq = sh[0][64+c]+sh[1][64+c]+sh[2][64+c]+sh[3][64+c];
        atomicAdd(&stat[c], ts);
        atomicAdd(&stat[64+c], tq);
    }
}

__device__ __forceinline__ float4 bn4(float4 x, float4 s1, float4 s2,
                                      float4 gg, float4 bb, float invn)
{
    float4 o;
    float mu = s1.x*invn, var = s2.x*invn - mu*mu;
    o.x = (x.x-mu)*rsqrtf(var+1e-5f)*gg.x + bb.x;
    mu = s1.y*invn; var = s2.y*invn - mu*mu;
    o.y = (x.y-mu)*rsqrtf(var+1e-5f)*gg.y + bb.y;
    mu = s1.z*invn; var = s2.z*invn - mu*mu;
    o.z = (x.z-mu)*rsqrtf(var+1e-5f)*gg.z + bb.z;
    mu = s1.w*invn; var = s2.w*invn - mu*mu;
    o.w = (x.w-mu)*rsqrtf(var+1e-5f)*gg.w + bb.w;
    return o;
}

__global__ void k_bnapply(const float* __restrict__ X, const float* __restrict__ stat,
                          const float* __restrict__ g, const float* __restrict__ b,
                          float* __restrict__ Y, int nq, float invn, int act)
{
    int i = blockIdx.x*blockDim.x + threadIdx.x;
    if (i >= nq) return;
    int c4 = i & 15;
    float4 o = bn4(((const float4*)X)[i], ((const float4*)stat)[c4],
                   ((const float4*)stat)[16+c4], ((const float4*)g)[c4],
                   ((const float4*)b)[c4], invn);
    if (act) { o.x=lrelu(o.x,0.01f); o.y=lrelu(o.y,0.01f);
               o.z=lrelu(o.z,0.01f); o.w=lrelu(o.w,0.01f); }
    ((float4*)Y)[i] = o;
}

__global__ void k_bnapply_uie(const float* __restrict__ X, const float* __restrict__ stat,
                              const float* __restrict__ g, const float* __restrict__ b,
                              float* __restrict__ ebn, float* __restrict__ uie, float invn)
{
    int i = blockIdx.x*blockDim.x + threadIdx.x;
    if (i >= NNODESN*16) return;
    int c4 = i & 15;
    float4 o = bn4(((const float4*)X)[i], ((const float4*)stat)[c4],
                   ((const float4*)stat)[16+c4], ((const float4*)g)[c4],
                   ((const float4*)b)[c4], invn);
    ((float4*)ebn)[i] = o;
    int row = i >> 4;
    if (row < NPREDN) ((float4*)uie)[i] = o;
    else if (row >= NNODESN - 100000)
        ((float4*)uie)[(size_t)(row - (NNODESN - NUIN))*16 + c4] = o;
}

// ================= counting sort by dst (CSR build) =================
__global__ void k_hist(const int* __restrict__ dst, int ne, int* __restrict__ cnt)
{
    int i = blockIdx.x*blockDim.x + threadIdx.x;
    if (i < ne) atomicAdd(&cnt[dst[i]], 1);
}
__global__ void k_scan_part(const int* __restrict__ cnt, int n, int* __restrict__ part)
{
    __shared__ int sh[256];
    int t = threadIdx.x, base = blockIdx.x*1024 + t*4;
    int s = 0;
    #pragma unroll
    for (int j = 0; j < 4; j++) { int i = base+j; if (i < n) s += cnt[i]; }
    sh[t] = s; __syncthreads();
    #pragma unroll
    for (int off = 128; off; off >>= 1) {
        if (t < off) sh[t] += sh[t+off];
        __syncthreads();
    }
    if (!t) part[blockIdx.x] = sh[0];
}
__global__ void k_scan_top(int* __restrict__ part, int nb, int* __restrict__ totptr)
{
    __shared__ int sh[256];
    int t = threadIdx.x;
    int v = t < nb ? part[t] : 0;
    sh[t] = v; __syncthreads();
    for (int off = 1; off < 256; off <<= 1) {
        int u = t >= off ? sh[t-off] : 0;
        __syncthreads();
        sh[t] += u;
        __syncthreads();
    }
    int excl = t ? sh[t-1] : 0;
    if (t < nb) part[t] = excl;
    if (t == 255) *totptr = sh[255];
}
__global__ void k_scan_final(const int* __restrict__ cnt, const int* __restrict__ part, int n,
                             int* __restrict__ rowptr, int* __restrict__ pos)
{
    __shared__ int sh[256];
    int t = threadIdx.x, base = blockIdx.x*1024 + t*4;
    int c[4]; int s = 0;
    #pragma unroll
    for (int j = 0; j < 4; j++) { int i = base+j; c[j] = (i < n) ? cnt[i] : 0; s += c[j]; }
    sh[t] = s; __syncthreads();
    for (int off = 1; off < 256; off <<= 1) {
        int u = t >= off ? sh[t-off] : 0;
        __syncthreads();
        sh[t] += u;
        __syncthreads();
    }
    int run = (t ? sh[t-1] : 0) + part[blockIdx.x];
    #pragma unroll
    for (int j = 0; j < 4; j++) {
        int i = base+j;
        if (i < n) { rowptr[i] = run; pos[i] = run; }
        run += c[j];
    }
}
__global__ void k_scatter(const int* __restrict__ src, const int* __restrict__ dst, int ne,
                          int* __restrict__ pos, int* __restrict__ srcs)
{
    int i = blockIdx.x*blockDim.x + threadIdx.x;
    if (i >= ne) return;
    int p = atomicAdd(&pos[dst[i]], 1);
    srcs[p] = src[i];
}
__global__ void k_deginv(const int* __restrict__ rowptr, float* __restrict__ dinv, int n)
{
    int i = blockIdx.x*blockDim.x + threadIdx.x;
    if (i < n) dinv[i] = rsqrtf(fmaxf((float)(rowptr[i+1]-rowptr[i]), 1.f));
}
__global__ void k_scatter_norm(const int* __restrict__ src, const int* __restrict__ dst, int ne,
                               int* __restrict__ pos, const float* __restrict__ dinv,
                               int* __restrict__ srcs, float* __restrict__ normv)
{
    int i = blockIdx.x*blockDim.x + threadIdx.x;
    if (i >= ne) return;
    int s = src[i], d = dst[i];
    int p = atomicAdd(&pos[d], 1);
    srcs[p] = s;
    normv[p] = dinv[s]*dinv[d];
}

// ================= node-parallel GAT aggregation (warp per dst node) =================
__global__ void k_gat_node(const int* __restrict__ rowptr, const int* __restrict__ srcs,
                           const float* __restrict__ fs, const float* __restrict__ fd,
                           const float* __restrict__ attn, float* __restrict__ out, int n)
{
    int w = (blockIdx.x*blockDim.x + threadIdx.x) >> 5;
    int lane = threadIdx.x & 31;
    if (w >= n) return;
    int beg = rowptr[w], end = rowptr[w+1];
    float2 fdv = ((const float2*)fd)[(size_t)w*32 + lane];
    float2 at  = ((const float2*)attn)[lane];
    float ax = 0.f, ay = 0.f, den = 0.f;
    int e = beg;
    for (; e+2 <= end; e += 2) {
        int s0 = srcs[e], s1 = srcs[e+1];
        float2 f0 = ((const float2*)fs)[(size_t)s0*32 + lane];
        float2 f1 = ((const float2*)fs)[(size_t)s1*32 + lane];
        float t0 = lrelu(f0.x+fdv.x,0.2f)*at.x + lrelu(f0.y+fdv.y,0.2f)*at.y;
        float t1 = lrelu(f1.x+fdv.x,0.2f)*at.x + lrelu(f1.y+fdv.y,0.2f)*at.y;
        #pragma unroll
        for (int o = 16; o; o >>= 1) {
            t0 += __shfl_xor_sync(0xffffffffu, t0, o);
            t1 += __shfl_xor_sync(0xffffffffu, t1, o);
        }
        float e0 = __expf(t0), e1 = __expf(t1);
        den += e0 + e1;
        ax += e0*f0.x + e1*f1.x;
        ay += e0*f0.y + e1*f1.y;
    }
    if (e < end) {
        int s0 = srcs[e];
        float2 f0 = ((const float2*)fs)[(size_t)s0*32 + lane];
        float t0 = lrelu(f0.x+fdv.x,0.2f)*at.x + lrelu(f0.y+fdv.y,0.2f)*at.y;
        #pragma unroll
        for (int o = 16; o; o >>= 1) t0 += __shfl_xor_sync(0xffffffffu, t0, o);
        float e0 = __expf(t0);
        den += e0; ax += e0*f0.x; ay += e0*f0.y;
    }
    float inv = den > 0.f ? 1.f/den : 0.f;
    ((float2*)out)[(size_t)w*32 + lane] =
        make_float2(lrelu(ax*inv,0.01f), lrelu(ay*inv,0.01f));
}

// node-parallel lhat: out = (2/lam)*(v - A_norm v) - v
__global__ void k_lhat_node(const int* __restrict__ rowptr, const int* __restrict__ srcs,
                            const float* __restrict__ normv, const float* __restrict__ v,
                            const float* __restrict__ lamp, float* __restrict__ out, int n)
{
    int w = (blockIdx.x*blockDim.x + threadIdx.x) >> 5;
    int lane = threadIdx.x & 31;
    if (w >= n) return;
    int beg = rowptr[w], end = rowptr[w+1];
    float ax = 0.f, ay = 0.f;
    int e = beg;
    for (; e+2 <= end; e += 2) {
        int s0 = srcs[e], s1 = srcs[e+1];
        float n0 = normv[e], n1 = normv[e+1];
        float2 f0 = ((const float2*)v)[(size_t)s0*32 + lane];
        float2 f1 = ((const float2*)v)[(size_t)s1*32 + lane];
        ax += n0*f0.x + n1*f1.x;
        ay += n0*f0.y + n1*f1.y;
    }
    if (e < end) {
        int s0 = srcs[e];
        float n0 = normv[e];
        float2 f0 = ((const float2*)v)[(size_t)s0*32 + lane];
        ax += n0*f0.x; ay += n0*f0.y;
    }
    float c = 2.f / __ldg(lamp);
    float2 vv = ((const float2*)v)[(size_t)w*32 + lane];
    ((float2*)out)[(size_t)w*32 + lane] =
        make_float2(c*(vv.x-ax)-vv.x, c*(vv.y-ay)-vv.y);
}

// ---------------- misc ----------------
__global__ void k_copy4(float* __restrict__ y, const float* __restrict__ x, int nq)
{
    int i = blockIdx.x*blockDim.x + threadIdx.x;
    if (i < nq) ((float4*)y)[i] = ((const float4*)x)[i];
}
__global__ void k_soc(const float* __restrict__ i2u, const int* __restrict__ ids,
                      float* __restrict__ soc, int n)
{
    int t = blockIdx.x*blockDim.x + threadIdx.x;
    int r = t >> 4, l = t & 15;
    if (r >= n) return;
    float4 v = ((const float4*)i2u)[(size_t)r*16 + l];
    float s = v.x + v.y + v.z + v.w;
    #pragma unroll
    for (int o = 8; o; o >>= 1) s += __shfl_xor_sync(0xffffffffu, s, o, 16);
    if (s != 0.f) {
        int tr = ids[r];
        ((float4*)soc)[(size_t)tr*16 + l] = v;
    }
}
__global__ void k_softmul(const float* __restrict__ hX, const float* __restrict__ hP,
                          const float* __restrict__ hS, float* __restrict__ out, int n)
{
    int t = blockIdx.x*blockDim.x + threadIdx.x;
    int r = t >> 4, l = t & 15;
    bool valid = r < n;
    size_t base = (size_t)(valid ? r : 0)*16 + l;
    float4 x = ((const float4*)hX)[base];
    float m = fmaxf(fmaxf(x.x, x.y), fmaxf(x.z, x.w));
    #pragma unroll
    for (int o = 8; o; o >>= 1) m = fmaxf(m, __shfl_xor_sync(0xffffffffu, m, o, 16));
    float4 e;
    e.x = __expf(x.x-m); e.y = __expf(x.y-m); e.z = __expf(x.z-m); e.w = __expf(x.w-m);
    float s = e.x + e.y + e.z + e.w;
    #pragma unroll
    for (int o = 8; o; o >>= 1) s += __shfl_xor_sync(0xffffffffu, s, o, 16);
    if (!valid) return;
    float inv = 1.f/s;
    float4 p = ((const float4*)hP)[base];
    float4 q = ((const float4*)hS)[base];
    ((float4*)out)[base] = make_float4(p.x*q.x*e.x*inv, p.y*q.y*e.y*inv,
                                       p.z*q.z*e.z*inv, p.w*q.w*e.w*inv);
}

// ---------------- host-side composition ----------------
struct Bufs {
    float *ebn,*uie,*fs,*fd,*gout,*u2i,*rc,*T1,*T2,*ch,*ch2,*i2u,*soc,*sie,
          *uitem,*huP,*huS,*mA,*z,*stat,*deginv,*normv;
    int *srcs,*rowptr,*cnt,*pos,*part;
};
static void get_bufs(Bufs& B) {
    cudaGetSymbolAddress((void**)&B.ebn,  g_ebn);
    cudaGetSymbolAddress((void**)&B.uie,  g_uie);
    cudaGetSymbolAddress((void**)&B.fs,   g_fs);
    cudaGetSymbolAddress((void**)&B.fd,   g_fd);
    cudaGetSymbolAddress((void**)&B.gout, g_gout);
    cudaGetSymbolAddress((void**)&B.u2i,  g_u2i);
    cudaGetSymbolAddress((void**)&B.rc,   g_rc);
    cudaGetSymbolAddress((void**)&B.T1,   g_T1);
    cudaGetSymbolAddress((void**)&B.T2,   g_T2);
    cudaGetSymbolAddress((void**)&B.ch,   g_ch);
    cudaGetSymbolAddress((void**)&B.ch2,  g_ch2);
    cudaGetSymbolAddress((void**)&B.i2u,  g_i2u);
    cudaGetSymbolAddress((void**)&B.soc,  g_soc);
    cudaGetSymbolAddress((void**)&B.sie,  g_sie);
    cudaGetSymbolAddress((void**)&B.uitem,g_uitem);
    cudaGetSymbolAddress((void**)&B.huP,  g_huP);
    cudaGetSymbolAddress((void**)&B.huS,  g_huS);
    cudaGetSymbolAddress((void**)&B.mA,   g_mA);
    cudaGetSymbolAddress((void**)&B.z,    g_z);
    cudaGetSymbolAddress((void**)&B.stat, g_stat);
    cudaGetSymbolAddress((void**)&B.deginv, g_deginv);
    cudaGetSymbolAddress((void**)&B.normv,  g_normv);
    cudaGetSymbolAddress((void**)&B.srcs,   g_srcs);
    cudaGetSymbolAddress((void**)&B.rowptr, g_rowptr);
    cudaGetSymbolAddress((void**)&B.cnt,    g_cnt);
    cudaGetSymbolAddress((void**)&B.pos,    g_pos);
    cudaGetSymbolAddress((void**)&B.part,   g_part);
}

// counting sort graph by dst; writes rowptr[0..n] and sorted srcs
static void sort_graph(Bufs& B, const int* src, const int* dst, int ne, int n,
                       int* rowptr, int* srcs, bool with_norm)
{
    cudaMemsetAsync(B.cnt, 0, (size_t)n*4);
    k_hist<<<ceil_div(ne,256),256>>>(dst, ne, B.cnt);
    int nb = ceil_div(n, 1024);
    k_scan_part<<<nb,256>>>(B.cnt, n, B.part);
    k_scan_top<<<1,256>>>(B.part, nb, rowptr + n);
    k_scan_final<<<nb,256>>>(B.cnt, B.part, n, rowptr, B.pos);
    if (with_norm) {
        k_deginv<<<ceil_div(n,256),256>>>(rowptr, B.deginv, n);
        k_scatter_norm<<<ceil_div(ne,256),256>>>(src, dst, ne, B.pos, B.deginv,
                                                 srcs, B.normv);
    } else {
        k_scatter<<<ceil_div(ne,256),256>>>(src, dst, ne, B.pos, srcs);
    }
}

static void run_gat(Bufs& B, const int* rowptr, const int* srcs,
                    const float* x, const int* ids, int n,
                    const float* Wl, const float* bl,
                    const float* Wr, const float* br,
                    const float* attn, float* out)
{
    k_gemm_dual<<<ceil_div(n,64),128>>>(x, ids, Wl, bl, B.fs, Wr, br, B.fd, n);
    k_gat_node<<<ceil_div(n,8),256>>>(rowptr, srcs, B.fs, B.fd, attn, out, n);
}

static void run_mlp(Bufs& B, const float* A, const float* Bx, const float* W,
                    const float* b, const float* g, const float* beta,
                    float* out, int n, float* stat)
{
    k_gemm_cat<<<ceil_div(n,64),128>>>(A, Bx, W, b, B.z, n, stat);
    k_bnapply<<<ceil_div(n*16,256),256>>>(B.z, stat, g, beta, out, n*16, 1.0f/n, 1);
}

extern "C" void kernel_launch(void* const* d_in, const int* in_sizes, int n_in,
                              void* d_out, int out_size)
{
    const float* emb      = (const float*)d_in[0];
    const float* bn0_g    = (const float*)d_in[1];
    const float* bn0_b    = (const float*)d_in[2];
    const float* gat_Wl   = (const float*)d_in[3];
    const float* gat_bl   = (const float*)d_in[4];
    const float* gat_Wr   = (const float*)d_in[5];
    const float* gat_br   = (const float*)d_in[6];
    const float* gat_attn = (const float*)d_in[7];
    const float* cheb_W   = (const float*)d_in[8];
    const float* cheb_b   = (const float*)d_in[9];
    const float* mlp_W    = (const float*)d_in[10];
    const float* mlp_b    = (const float*)d_in[11];
    const float* mlp_g    = (const float*)d_in[12];
    const float* mlp_beta = (const float*)d_in[13];
    const float* lam      = (const float*)d_in[14];
    const int* u2i_src = (const int*)d_in[15]; const int* u2i_dst = (const int*)d_in[16];
    const int* rc_src  = (const int*)d_in[17]; const int* rc_dst  = (const int*)d_in[18];
    const int* i2u_src = (const int*)d_in[19]; const int* i2u_dst = (const int*)d_in[20];
    const int* i2u_ids = (const int*)d_in[21];
    const int* sn_src  = (const int*)d_in[22]; const int* sn_dst  = (const int*)d_in[23];
    const int* snn_src = (const int*)d_in[24]; const int* snn_dst = (const int*)d_in[25];

    int ne_u2i = in_sizes[15], ne_rc = in_sizes[17], ne_i2u = in_sizes[19];
    int ne_sn  = in_sizes[22], ne_snn = in_sizes[24];

    float* out = (float*)d_out;
    Bufs B; get_bufs(B);

    // CSR slots
    int* rp_u2i = B.rowptr + 0*RPSZ; int* sc_u2i = B.srcs + 0;
    int* rp_rc  = B.rowptr + 1*RPSZ; int* sc_rc  = B.srcs + 1500000;
    int* rp_i2u = B.rowptr + 2*RPSZ; int* sc_i2u = B.srcs + 3000000;
    int* rp_sn  = B.rowptr + 3*RPSZ; int* sc_sn  = B.srcs + 4000000;
    int* rp_snn = B.rowptr + 4*RPSZ; int* sc_snn = B.srcs + 5000000;

    cudaMemsetAsync(B.stat, 0, 6*128*4);

    // sorts (independent of features)
    sort_graph(B, u2i_src, u2i_dst, ne_u2i, NUIN,   rp_u2i, sc_u2i, false);
    sort_graph(B, rc_src,  rc_dst,  ne_rc,  NUIN,   rp_rc,  sc_rc,  false);
    sort_graph(B, i2u_src, i2u_dst, ne_i2u, NPREDN, rp_i2u, sc_i2u, false);
    sort_graph(B, sn_src,  sn_dst,  ne_sn,  NPREDN, rp_sn,  sc_sn,  false);
    sort_graph(B, snn_src, snn_dst, ne_snn, NTOTN,  rp_snn, sc_snn, true);

    // 1. e = BN(emb); fused uie
    k_colstats<<<512,256>>>(emb, NNODESN, B.stat);
    k_bnapply_uie<<<ceil_div(NNODESN*16,256),256>>>(emb, B.stat, bn0_g, bn0_b,
                                                    B.ebn, B.uie, 1.0f/NNODESN);

    // 2. GAT0 (u2i), GAT1 (rc)
    run_gat(B, rp_u2i, sc_u2i, B.uie, nullptr, NUIN,
            gat_Wl+0*4096, gat_bl+0*64, gat_Wr+0*4096, gat_br+0*64, gat_attn+0*64, B.u2i);
    run_gat(B, rp_rc, sc_rc, B.u2i, nullptr, NUIN,
            gat_Wl+1*4096, gat_bl+1*64, gat_Wr+1*4096, gat_br+1*64, gat_attn+1*64, B.rc);

    // 3. GAT2 on su = uie[i2u_ids]
    run_gat(B, rp_i2u, sc_i2u, B.uie, i2u_ids, NPREDN,
            gat_Wl+2*4096, gat_bl+2*64, gat_Wr+2*4096, gat_br+2*64, gat_attn+2*64, B.i2u);

    // 4. soc
    k_copy4<<<ceil_div(NPREDN*16,256),256>>>(B.soc, B.uie, NPREDN*16);
    k_soc<<<ceil_div(NPREDN*16,256),256>>>(B.i2u, i2u_ids, B.soc, NPREDN);

    // 5. GAT3 (sn)
    run_gat(B, rp_sn, sc_sn, B.soc, nullptr, NPREDN,
            gat_Wl+3*4096, gat_bl+3*64, gat_Wr+3*4096, gat_br+3*64, gat_attn+3*64, B.sie);

    // 6. user_item_embed = mlp0([iie, sie])
    run_mlp(B, B.rc, B.sie, mlp_W+0*8192, mlp_b+0*64, mlp_g+0*64, mlp_beta+0*64,
            B.uitem, NPREDN, B.stat + 128);

    // 7. Cheb layer 1 (T0 = ebn[:TOTAL])
    k_lhat_node<<<ceil_div(NTOTN,8),256>>>(rp_snn, sc_snn, B.normv, B.ebn, lam, B.T1, NTOTN);
    k_lhat_node<<<ceil_div(NTOTN,8),256>>>(rp_snn, sc_snn, B.normv, B.T1,  lam, B.T2, NTOTN);
    k_gemm_cat3<<<ceil_div(NTOTN,64),128>>>(B.ebn, B.T1, B.T2, cheb_W, cheb_b, B.ch, NTOTN);

    // 8. Cheb layer 2
    k_lhat_node<<<ceil_div(NTOTN,8),256>>>(rp_snn, sc_snn, B.normv, B.ch, lam, B.T1, NTOTN);
    k_lhat_node<<<ceil_div(NTOTN,8),256>>>(rp_snn, sc_snn, B.normv, B.T1, lam, B.T2, NTOTN);
    k_gemm_cat3<<<ceil_div(NTOTN,64),128>>>(B.ch, B.T1, B.T2, cheb_W, cheb_b, B.ch2, NTOTN);

    // 9. GAT4 (snn)
    run_gat(B, rp_snn, sc_snn, B.ch2, nullptr, NTOTN,
            gat_Wl+4*4096, gat_bl+4*64, gat_Wr+4*4096, gat_br+4*64, gat_attn+4*64, B.gout);

    // 10. h_uP, h_uS
    run_mlp(B, B.uitem, B.ebn, mlp_W+1*8192, mlp_b+1*64, mlp_g+1*64, mlp_beta+1*64,
            B.huP, NPREDN, B.stat + 2*128);
    run_mlp(B, B.gout,  B.ebn, mlp_W+2*8192, mlp_b+2*64, mlp_g+2*64, mlp_beta+2*64,
            B.huS, NPREDN, B.stat + 3*128);

    // 11. gating + final MLPs
    k_softmul<<<ceil_div(NPREDN*16,256),256>>>(B.huP, B.huP, B.huS, B.mA, NPREDN);
    run_mlp(B, B.mA, B.huP, mlp_W+3*8192, mlp_b+3*64, mlp_g+3*64, mlp_beta+3*64,
            out, NPREDN, B.stat + 4*128);
    k_softmul<<<ceil_div(NPREDN*16,256),256>>>(B.huS, B.huP, B.huS, B.mA, NPREDN);
    run_mlp(B, B.mA, B.huS, mlp_W+4*8192, mlp_b+4*64, mlp_g+4*64, mlp_beta+4*64,
            out + (size_t)NPREDN*EMBD, NPREDN, B.stat + 5*128);
}